// round 1
// baseline (speedup 1.0000x reference)
#include <cuda_runtime.h>
#include <math.h>

// Problem constants
#define B_ 32
#define T_ 512
#define D_ 512
#define H_ 8
#define M_ (B_ * T_)   // 16384 rows
#define F_ 2048

// ---------------------------------------------------------------------------
// Scratch (device globals; no allocation allowed)
// ---------------------------------------------------------------------------
__device__ float g_q  [(size_t)M_ * D_];
__device__ float g_k  [(size_t)M_ * D_];
__device__ float g_v  [(size_t)M_ * D_];
__device__ float g_at [(size_t)M_ * D_];
__device__ float g_tmp[(size_t)M_ * D_];
__device__ float g_Y  [(size_t)M_ * D_];
__device__ float g_Z  [(size_t)M_ * D_];
__device__ float g_ffn[(size_t)M_ * F_];

// ---------------------------------------------------------------------------
// GEMM: C[M,N] = A[M,K] @ W[N,K]^T  (+bias over N, +leaky-relu)
// Tiles: 128x128x16, 256 threads, 8x8 register micro-tile per thread.
// M, N divisible by 128; K divisible by 16 (holds for all shapes here).
// ---------------------------------------------------------------------------
template <int BIAS, int LEAKY>
__global__ void __launch_bounds__(256, 2)
gemm_tn(const float* __restrict__ A, const float* __restrict__ W,
        const float* __restrict__ bias, float* __restrict__ C,
        int N, int K)
{
    __shared__ __align__(16) float sA[16][132];
    __shared__ __align__(16) float sB[16][132];

    const int tid = threadIdx.x;
    const int bm = blockIdx.y * 128;
    const int bn = blockIdx.x * 128;
    const int tx = tid & 15, ty = tid >> 4;
    const int lrow = tid >> 2;            // 0..63
    const int lcol = (tid & 3) << 2;      // 0,4,8,12

    float acc[8][8];
#pragma unroll
    for (int i = 0; i < 8; i++)
#pragma unroll
        for (int j = 0; j < 8; j++) acc[i][j] = 0.f;

    const float* Ap = A + (size_t)(bm + lrow) * K + lcol;
    const float* Wp = W + (size_t)(bn + lrow) * K + lcol;

    for (int k0 = 0; k0 < K; k0 += 16) {
#pragma unroll
        for (int i = 0; i < 2; i++) {
            float4 va = *(const float4*)(Ap + (size_t)i * 64 * K + k0);
            float4 vb = *(const float4*)(Wp + (size_t)i * 64 * K + k0);
            int r = lrow + i * 64;
            sA[lcol + 0][r] = va.x; sA[lcol + 1][r] = va.y;
            sA[lcol + 2][r] = va.z; sA[lcol + 3][r] = va.w;
            sB[lcol + 0][r] = vb.x; sB[lcol + 1][r] = vb.y;
            sB[lcol + 2][r] = vb.z; sB[lcol + 3][r] = vb.w;
        }
        __syncthreads();
#pragma unroll
        for (int kk = 0; kk < 16; kk++) {
            float a[8], b[8];
            *(float4*)(a)     = *(const float4*)&sA[kk][ty * 8];
            *(float4*)(a + 4) = *(const float4*)&sA[kk][ty * 8 + 4];
            *(float4*)(b)     = *(const float4*)&sB[kk][tx * 8];
            *(float4*)(b + 4) = *(const float4*)&sB[kk][tx * 8 + 4];
#pragma unroll
            for (int i = 0; i < 8; i++)
#pragma unroll
                for (int j = 0; j < 8; j++)
                    acc[i][j] += a[i] * b[j];
        }
        __syncthreads();
    }

#pragma unroll
    for (int i = 0; i < 8; i++) {
        const int row = bm + ty * 8 + i;
#pragma unroll
        for (int j0 = 0; j0 < 8; j0 += 4) {
            const int col = bn + tx * 8 + j0;
            float4 v = make_float4(acc[i][j0], acc[i][j0 + 1],
                                   acc[i][j0 + 2], acc[i][j0 + 3]);
            if (BIAS) {
                v.x += bias[col];     v.y += bias[col + 1];
                v.z += bias[col + 2]; v.w += bias[col + 3];
            }
            if (LEAKY) {
                v.x = v.x > 0.f ? v.x : 0.01f * v.x;
                v.y = v.y > 0.f ? v.y : 0.01f * v.y;
                v.z = v.z > 0.f ? v.z : 0.01f * v.z;
                v.w = v.w > 0.f ? v.w : 0.01f * v.w;
            }
            *(float4*)&C[(size_t)row * N + col] = v;
        }
    }
}

// ---------------------------------------------------------------------------
// Fused attention (flash-style online softmax), fp32.
// Grid: (B*H, T/64). Block: 256 threads.
// Each block: 64 q-rows of one head; streams K/V in 64-row tiles.
// Thread (tx,ty) in a 16x16 grid owns a 4x4 micro-tile of both the 64x64
// score tile and the 64x64 output tile. Masking: key index < valid_len
// (valid keys are a prefix, so the running max is real before masked tiles).
// ---------------------------------------------------------------------------
__global__ void __launch_bounds__(256)
attn_kernel(const float* __restrict__ Q, const float* __restrict__ K,
            const float* __restrict__ V, const int* __restrict__ vl,
            int per_row, float* __restrict__ O)
{
    extern __shared__ __align__(16) float smem[];
    float (*sQt)[68] = (float(*)[68])(smem);               // [d][r]
    float (*sKt)[68] = (float(*)[68])(smem + 64 * 68);     // [d][c]
    float (*sV )[68] = (float(*)[68])(smem + 2 * 64 * 68); // [k][c]
    float (*sP )[68] = (float(*)[68])(smem + 3 * 64 * 68); // [k][r]

    const int tid = threadIdx.x;
    const int bh = blockIdx.x;
    const int b = bh >> 3, h = bh & 7;
    const int q0 = blockIdx.y * 64;
    const int tx = tid & 15, ty = tid >> 4;
    const int tx4 = tx * 4, ty4 = ty * 4;

    // Load Q tile transposed
    const float* Qp = Q + (size_t)(b * T_ + q0) * D_ + h * 64;
    for (int i = tid; i < 64 * 16; i += 256) {
        int r = i >> 4;
        int d4 = (i & 15) * 4;
        float4 v = *(const float4*)(Qp + (size_t)r * D_ + d4);
        sQt[d4 + 0][r] = v.x; sQt[d4 + 1][r] = v.y;
        sQt[d4 + 2][r] = v.z; sQt[d4 + 3][r] = v.w;
    }

    int vlen[4];
#pragma unroll
    for (int ri = 0; ri < 4; ri++)
        vlen[ri] = per_row ? vl[b * T_ + q0 + ty4 + ri] : vl[b];

    float m[4], l[4], acc[4][4];
#pragma unroll
    for (int ri = 0; ri < 4; ri++) {
        m[ri] = -1e30f; l[ri] = 0.f;
#pragma unroll
        for (int cj = 0; cj < 4; cj++) acc[ri][cj] = 0.f;
    }

    for (int k0 = 0; k0 < T_; k0 += 64) {
        __syncthreads();  // protect sKt/sV/sP from previous iteration readers
        const float* Kp = K + (size_t)(b * T_ + k0) * D_ + h * 64;
        const float* Vp = V + (size_t)(b * T_ + k0) * D_ + h * 64;
        for (int i = tid; i < 64 * 16; i += 256) {
            int r = i >> 4;
            int d4 = (i & 15) * 4;
            float4 kv = *(const float4*)(Kp + (size_t)r * D_ + d4);
            sKt[d4 + 0][r] = kv.x; sKt[d4 + 1][r] = kv.y;
            sKt[d4 + 2][r] = kv.z; sKt[d4 + 3][r] = kv.w;
            *(float4*)&sV[r][d4] = *(const float4*)(Vp + (size_t)r * D_ + d4);
        }
        __syncthreads();

        // S = Q K^T  (4x4 per thread)
        float s[4][4];
#pragma unroll
        for (int ri = 0; ri < 4; ri++)
#pragma unroll
            for (int cj = 0; cj < 4; cj++) s[ri][cj] = 0.f;

#pragma unroll 8
        for (int d = 0; d < 64; d++) {
            float4 qv = *(const float4*)&sQt[d][ty4];
            float4 kv = *(const float4*)&sKt[d][tx4];
            const float qa[4] = {qv.x, qv.y, qv.z, qv.w};
            const float kb[4] = {kv.x, kv.y, kv.z, kv.w};
#pragma unroll
            for (int ri = 0; ri < 4; ri++)
#pragma unroll
                for (int cj = 0; cj < 4; cj++)
                    s[ri][cj] += qa[ri] * kb[cj];
        }

        // scale + mask + online softmax update (row stats shared by 16 tx
        // lanes of the same ty, butterfly-reduced within the 16-lane group)
#pragma unroll
        for (int ri = 0; ri < 4; ri++) {
#pragma unroll
            for (int cj = 0; cj < 4; cj++) {
                float sc = s[ri][cj] * 0.125f;
                int kidx = k0 + tx4 + cj;
                s[ri][cj] = (kidx < vlen[ri]) ? sc : -1.0e10f;
            }
            float rm = fmaxf(fmaxf(s[ri][0], s[ri][1]),
                             fmaxf(s[ri][2], s[ri][3]));
#pragma unroll
            for (int off = 8; off; off >>= 1)
                rm = fmaxf(rm, __shfl_xor_sync(0xffffffffu, rm, off));
            float mn = fmaxf(m[ri], rm);
            float alpha = __expf(m[ri] - mn);
            m[ri] = mn;
            float rs = 0.f;
#pragma unroll
            for (int cj = 0; cj < 4; cj++) {
                float p = __expf(s[ri][cj] - mn);
                s[ri][cj] = p;
                rs += p;
            }
#pragma unroll
            for (int off = 8; off; off >>= 1)
                rs += __shfl_xor_sync(0xffffffffu, rs, off);
            l[ri] = l[ri] * alpha + rs;
#pragma unroll
            for (int cj = 0; cj < 4; cj++) acc[ri][cj] *= alpha;
        }

        // Write P transposed: sP[k][r]
#pragma unroll
        for (int cj = 0; cj < 4; cj++)
            *(float4*)&sP[tx4 + cj][ty4] =
                make_float4(s[0][cj], s[1][cj], s[2][cj], s[3][cj]);
        __syncthreads();

        // acc += P V  (4x4 per thread)
#pragma unroll 8
        for (int k = 0; k < 64; k++) {
            float4 pv = *(const float4*)&sP[k][ty4];
            float4 vv = *(const float4*)&sV[k][tx4];
            const float pa[4] = {pv.x, pv.y, pv.z, pv.w};
            const float vb[4] = {vv.x, vv.y, vv.z, vv.w};
#pragma unroll
            for (int ri = 0; ri < 4; ri++)
#pragma unroll
                for (int cj = 0; cj < 4; cj++)
                    acc[ri][cj] += pa[ri] * vb[cj];
        }
    }

#pragma unroll
    for (int ri = 0; ri < 4; ri++) {
        float inv = 1.0f / l[ri];
        float4 o = make_float4(acc[ri][0] * inv, acc[ri][1] * inv,
                               acc[ri][2] * inv, acc[ri][3] * inv);
        *(float4*)&O[(size_t)(b * T_ + q0 + ty4 + ri) * D_ + h * 64 + tx4] = o;
    }
}

// ---------------------------------------------------------------------------
// out = LayerNorm(A + Bt) * g + be    (one block per row, 128 threads)
// var = E[x^2] - mu^2  (matches jnp.var, ddof=0), eps = 1e-5
// ---------------------------------------------------------------------------
__global__ void __launch_bounds__(128)
addnorm_kernel(const float* __restrict__ A, const float* __restrict__ Bt,
               const float* __restrict__ g, const float* __restrict__ be,
               float* __restrict__ out)
{
    const int row = blockIdx.x;
    const int tid = threadIdx.x;
    const size_t base = (size_t)row * D_;

    float4 a = *(const float4*)&A[base + tid * 4];
    float4 b = *(const float4*)&Bt[base + tid * 4];
    float4 x = make_float4(a.x + b.x, a.y + b.y, a.z + b.z, a.w + b.w);

    float s  = x.x + x.y + x.z + x.w;
    float sq = x.x * x.x + x.y * x.y + x.z * x.z + x.w * x.w;
#pragma unroll
    for (int off = 16; off; off >>= 1) {
        s  += __shfl_xor_sync(0xffffffffu, s,  off);
        sq += __shfl_xor_sync(0xffffffffu, sq, off);
    }
    __shared__ float ss[4], ssq[4];
    if ((tid & 31) == 0) { ss[tid >> 5] = s; ssq[tid >> 5] = sq; }
    __syncthreads();
    s  = ss[0] + ss[1] + ss[2] + ss[3];
    sq = ssq[0] + ssq[1] + ssq[2] + ssq[3];

    float mu  = s * (1.0f / D_);
    float var = sq * (1.0f / D_) - mu * mu;
    float inv = rsqrtf(var + 1e-5f);

    float4 gg = *(const float4*)&g[tid * 4];
    float4 bb = *(const float4*)&be[tid * 4];
    float4 o = make_float4((x.x - mu) * inv * gg.x + bb.x,
                           (x.y - mu) * inv * gg.y + bb.y,
                           (x.z - mu) * inv * gg.z + bb.z,
                           (x.w - mu) * inv * gg.w + bb.w);
    *(float4*)&out[base + tid * 4] = o;
}

// ---------------------------------------------------------------------------
// Launch
// ---------------------------------------------------------------------------
extern "C" void kernel_launch(void* const* d_in, const int* in_sizes, int n_in,
                              void* d_out, int out_size)
{
    const float* X    = (const float*)d_in[0];
    const float* ENC  = (const float*)d_in[1];
    const int*   DVL  = (const int*)d_in[2];
    const int*   EVL  = (const int*)d_in[3];
    const float* Wq1  = (const float*)d_in[4];
    const float* Wk1  = (const float*)d_in[5];
    const float* Wv1  = (const float*)d_in[6];
    const float* Wo1  = (const float*)d_in[7];
    const float* Wq2  = (const float*)d_in[8];
    const float* Wk2  = (const float*)d_in[9];
    const float* Wv2  = (const float*)d_in[10];
    const float* Wo2  = (const float*)d_in[11];
    const float* W1   = (const float*)d_in[12];
    const float* b1   = (const float*)d_in[13];
    const float* W2   = (const float*)d_in[14];
    const float* b2   = (const float*)d_in[15];
    const float* G1   = (const float*)d_in[16];
    const float* BE1  = (const float*)d_in[17];
    const float* G2   = (const float*)d_in[18];
    const float* BE2  = (const float*)d_in[19];
    const float* G3   = (const float*)d_in[20];
    const float* BE3  = (const float*)d_in[21];
    float* out = (float*)d_out;

    float *q, *k, *v, *at, *tmp, *Y, *Z, *ffn;
    cudaGetSymbolAddress((void**)&q,   g_q);
    cudaGetSymbolAddress((void**)&k,   g_k);
    cudaGetSymbolAddress((void**)&v,   g_v);
    cudaGetSymbolAddress((void**)&at,  g_at);
    cudaGetSymbolAddress((void**)&tmp, g_tmp);
    cudaGetSymbolAddress((void**)&Y,   g_Y);
    cudaGetSymbolAddress((void**)&Z,   g_Z);
    cudaGetSymbolAddress((void**)&ffn, g_ffn);

    const int ATT_SMEM = 4 * 64 * 68 * (int)sizeof(float);  // 69632 B
    cudaFuncSetAttribute(attn_kernel,
                         cudaFuncAttributeMaxDynamicSharedMemorySize, ATT_SMEM);

    dim3 gP (D_ / 128, M_ / 128);   // (4, 128)
    dim3 gF1(F_ / 128, M_ / 128);   // (16, 128)
    dim3 gA (B_ * H_,  T_ / 64);    // (256, 8)

    // ---- self-attention ----
    gemm_tn<0, 0><<<gP, 256>>>(X, Wq1, nullptr, q, D_, D_);
    gemm_tn<0, 0><<<gP, 256>>>(X, Wk1, nullptr, k, D_, D_);
    gemm_tn<0, 0><<<gP, 256>>>(X, Wv1, nullptr, v, D_, D_);
    attn_kernel<<<gA, 256, ATT_SMEM>>>(q, k, v, DVL, 1, at);
    gemm_tn<0, 0><<<gP, 256>>>(at, Wo1, nullptr, tmp, D_, D_);
    addnorm_kernel<<<M_, 128>>>(X, tmp, G1, BE1, Y);

    // ---- cross-attention ----
    gemm_tn<0, 0><<<gP, 256>>>(Y,   Wq2, nullptr, q, D_, D_);
    gemm_tn<0, 0><<<gP, 256>>>(ENC, Wk2, nullptr, k, D_, D_);
    gemm_tn<0, 0><<<gP, 256>>>(ENC, Wv2, nullptr, v, D_, D_);
    attn_kernel<<<gA, 256, ATT_SMEM>>>(q, k, v, EVL, 0, at);
    gemm_tn<0, 0><<<gP, 256>>>(at, Wo2, nullptr, tmp, D_, D_);
    addnorm_kernel<<<M_, 128>>>(Y, tmp, G2, BE2, Z);

    // ---- FFN ----
    gemm_tn<1, 1><<<gF1, 256>>>(Z,   W1, b1, ffn, F_, D_);
    gemm_tn<1, 0><<<gP,  256>>>(ffn, W2, b2, tmp, D_, F_);
    addnorm_kernel<<<M_, 128>>>(Z, tmp, G3, BE3, out);
}

// round 4
// speedup vs baseline: 1.8690x; 1.8690x over previous
#include <cuda_runtime.h>
#include <cuda_bf16.h>
#include <math.h>
#include <stdint.h>

// Problem constants
#define B_ 32
#define T_ 512
#define D_ 512
#define H_ 8
#define M_ (B_ * T_)   // 16384 rows
#define F_ 2048

// ---------------------------------------------------------------------------
// Scratch (device globals; no allocation allowed)
// ---------------------------------------------------------------------------
__device__ float g_q  [(size_t)M_ * D_];
__device__ float g_k  [(size_t)M_ * D_];
__device__ float g_v  [(size_t)M_ * D_];
__device__ float g_at [(size_t)M_ * D_];
__device__ float g_tmp[(size_t)M_ * D_];
__device__ float g_Y  [(size_t)M_ * D_];
__device__ float g_Z  [(size_t)M_ * D_];
__device__ float g_ffn[(size_t)M_ * F_];

// bf16 split buffers
__device__ __nv_bfloat16 g_Ah[(size_t)M_ * D_];
__device__ __nv_bfloat16 g_Al[(size_t)M_ * D_];
__device__ __nv_bfloat16 g_Bh[(size_t)M_ * D_];
__device__ __nv_bfloat16 g_Bl[(size_t)M_ * D_];
__device__ __nv_bfloat16 g_Fh[(size_t)M_ * F_];
__device__ __nv_bfloat16 g_Fl[(size_t)M_ * F_];
__device__ __nv_bfloat16 g_Wh[4194304];
__device__ __nv_bfloat16 g_Wl[4194304];

// ---------------------------------------------------------------------------
// helpers
// ---------------------------------------------------------------------------
__device__ __forceinline__ uint32_t smem_u32(const void* p) {
    uint32_t a;
    asm("{ .reg .u64 t; cvta.to.shared.u64 t, %1; cvt.u32.u64 %0, t; }"
        : "=r"(a) : "l"(p));
    return a;
}

#define CP_ASYNC16(dst, src) \
    asm volatile("cp.async.cg.shared.global [%0], [%1], 16;" :: \
                 "r"(dst), "l"(src) : "memory")
#define CP_COMMIT() asm volatile("cp.async.commit_group;" ::: "memory")
#define CP_WAIT(n)  asm volatile("cp.async.wait_group %0;" :: "n"(n) : "memory")

#define LDMATRIX_X4(r0, r1, r2, r3, addr) \
    asm volatile("ldmatrix.sync.aligned.m8n8.x4.shared.b16 {%0,%1,%2,%3}, [%4];" \
                 : "=r"(r0), "=r"(r1), "=r"(r2), "=r"(r3) : "r"(addr))

#define MMA_BF16(d0, d1, d2, d3, a0, a1, a2, a3, b0, b1) \
    asm volatile("mma.sync.aligned.m16n8k16.row.col.f32.bf16.bf16.f32 " \
                 "{%0,%1,%2,%3}, {%4,%5,%6,%7}, {%8,%9}, {%0,%1,%2,%3};" \
                 : "+f"(d0), "+f"(d1), "+f"(d2), "+f"(d3) \
                 : "r"(a0), "r"(a1), "r"(a2), "r"(a3), "r"(b0), "r"(b1))

// ---------------------------------------------------------------------------
// split: fp32 -> (bf16 hi, bf16 lo) with lo = bf16(x - float(hi))
// ---------------------------------------------------------------------------
__global__ void __launch_bounds__(256)
split_kernel(const float* __restrict__ x, __nv_bfloat16* __restrict__ hi,
             __nv_bfloat16* __restrict__ lo, int n4)
{
    int i = blockIdx.x * 256 + threadIdx.x;
    if (i >= n4) return;
    float4 v = ((const float4*)x)[i];
    __nv_bfloat16 h0 = __float2bfloat16(v.x);
    __nv_bfloat16 h1 = __float2bfloat16(v.y);
    __nv_bfloat16 h2 = __float2bfloat16(v.z);
    __nv_bfloat16 h3 = __float2bfloat16(v.w);
    __nv_bfloat16 l0 = __float2bfloat16(v.x - __bfloat162float(h0));
    __nv_bfloat16 l1 = __float2bfloat16(v.y - __bfloat162float(h1));
    __nv_bfloat16 l2 = __float2bfloat16(v.z - __bfloat162float(h2));
    __nv_bfloat16 l3 = __float2bfloat16(v.w - __bfloat162float(h3));
    __nv_bfloat162* hp = (__nv_bfloat162*)hi;
    __nv_bfloat162* lp = (__nv_bfloat162*)lo;
    hp[2 * i]     = __nv_bfloat162(h0, h1);
    hp[2 * i + 1] = __nv_bfloat162(h2, h3);
    lp[2 * i]     = __nv_bfloat162(l0, l1);
    lp[2 * i + 1] = __nv_bfloat162(l2, l3);
}

// ---------------------------------------------------------------------------
// HMMA GEMM: C[M,N] = (Ah+Al)[M,K] @ (Bh+Bl)[N,K]^T  (3-pass bf16 split)
// 128x128 CTA tile, 8 warps (2 x 4), 64x32 warp tile, BK=32,
// cp.async double buffer. SMEM rows: 32 bf16 data + pad -> 80 B stride
// (odd # of 16B chunks => conflict-free ldmatrix).
// ---------------------------------------------------------------------------
#define ROWB 80                      // bytes per smem row
#define TILE_B (128 * ROWB)          // 10240 B per tile
#define STAGE_B (4 * TILE_B)         // Ah, Al, Bh, Bl
#define GEMM_SMEM (2 * STAGE_B)      // 81920 B

template <int BIAS, int LEAKY>
__global__ void __launch_bounds__(256, 2)
gemm_hmma(const __nv_bfloat16* __restrict__ Ah, const __nv_bfloat16* __restrict__ Al,
          const __nv_bfloat16* __restrict__ Bh, const __nv_bfloat16* __restrict__ Bl,
          const float* __restrict__ bias, float* __restrict__ C,
          int N, int K)
{
    extern __shared__ __align__(16) char smem[];
    const uint32_t sbase = smem_u32(smem);

    const int tid = threadIdx.x;
    const int wid = tid >> 5, lane = tid & 31;
    const int wm = wid & 1, wn = wid >> 1;         // 2 x 4 warp grid
    const int bm = blockIdx.y * 128;
    const int bn = blockIdx.x * 128;

    // cp.async mapping: per tile 512 16B chunks; thread does 2 per tile.
    const int ldr0 = tid >> 2;            // row 0..63
    const int ldc  = (tid & 3) * 8;       // element col 0,8,16,24
    const int ldco = (tid & 3) * 16;      // byte col in smem row

    const __nv_bfloat16* gAh = Ah + (size_t)(bm + ldr0) * K + ldc;
    const __nv_bfloat16* gAl = Al + (size_t)(bm + ldr0) * K + ldc;
    const __nv_bfloat16* gBh = Bh + (size_t)(bn + ldr0) * K + ldc;
    const __nv_bfloat16* gBl = Bl + (size_t)(bn + ldr0) * K + ldc;
    const size_t rstep = (size_t)64 * K;  // +64 rows

    // ldmatrix lane geometry
    const int aRow = lane & 15;           // A: rows m0..15
    const int aK8  = (lane >> 4) * 16;    //     k offset bytes (+8 elems)
    const int bMat = lane >> 3;
    const int bRow = (lane & 7) + ((bMat >> 1) << 3);   // B: n row
    const int bK8  = (bMat & 1) * 16;                   //     k offset bytes

    float acc[4][4][4];
#pragma unroll
    for (int i = 0; i < 4; i++)
#pragma unroll
        for (int j = 0; j < 4; j++)
#pragma unroll
            for (int r = 0; r < 4; r++) acc[i][j][r] = 0.f;

    const int NC = K >> 5;   // chunks of 32

    auto load_chunk = [&](int c) {
        const uint32_t st = sbase + (c & 1) * STAGE_B;
        const int koff = c << 5;
#pragma unroll
        for (int h = 0; h < 2; h++) {
            const int r = ldr0 + h * 64;
            const uint32_t sro = r * ROWB + ldco;
            CP_ASYNC16(st + sro,              gAh + (size_t)h * rstep + koff);
            CP_ASYNC16(st + TILE_B + sro,     gAl + (size_t)h * rstep + koff);
            CP_ASYNC16(st + 2 * TILE_B + sro, gBh + (size_t)h * rstep + koff);
            CP_ASYNC16(st + 3 * TILE_B + sro, gBl + (size_t)h * rstep + koff);
        }
        CP_COMMIT();
    };

    load_chunk(0);

    for (int c = 0; c < NC; c++) {
        if (c + 1 < NC) { load_chunk(c + 1); CP_WAIT(1); }
        else            { CP_WAIT(0); }
        __syncthreads();

        const uint32_t st = sbase + (c & 1) * STAGE_B;
        const uint32_t sA[2] = { st,              st + TILE_B };       // hi, lo
        const uint32_t sB[2] = { st + 2 * TILE_B, st + 3 * TILE_B };

#pragma unroll
        for (int pass = 0; pass < 3; pass++) {
            const uint32_t aB = sA[pass == 2 ? 1 : 0];
            const uint32_t bB = sB[pass == 1 ? 1 : 0];
#pragma unroll
            for (int ks = 0; ks < 2; ks++) {
                // B frags: 2 x ldmatrix.x4 covering n=0..31 of warp tile
                uint32_t b[4][2];
#pragma unroll
                for (int j2 = 0; j2 < 2; j2++) {
                    const uint32_t addr = bB +
                        (wn * 32 + j2 * 16 + bRow) * ROWB + ks * 32 + bK8;
                    uint32_t r0, r1, r2, r3;
                    LDMATRIX_X4(r0, r1, r2, r3, addr);
                    b[j2 * 2 + 0][0] = r0; b[j2 * 2 + 0][1] = r1;
                    b[j2 * 2 + 1][0] = r2; b[j2 * 2 + 1][1] = r3;
                }
                // A frags + mma
#pragma unroll
                for (int i = 0; i < 4; i++) {
                    const uint32_t addr = aB +
                        (wm * 64 + i * 16 + aRow) * ROWB + ks * 32 + aK8;
                    uint32_t a0, a1, a2, a3;
                    LDMATRIX_X4(a0, a1, a2, a3, addr);
#pragma unroll
                    for (int j = 0; j < 4; j++)
                        MMA_BF16(acc[i][j][0], acc[i][j][1],
                                 acc[i][j][2], acc[i][j][3],
                                 a0, a1, a2, a3, b[j][0], b[j][1]);
                }
            }
        }
        __syncthreads();
    }

    // epilogue
    const int tg = lane >> 2;     // 0..7 (row within frag)
    const int tc = (lane & 3) * 2;
#pragma unroll
    for (int i = 0; i < 4; i++) {
        const int r0 = bm + wm * 64 + i * 16 + tg;
#pragma unroll
        for (int j = 0; j < 4; j++) {
            const int col = bn + wn * 32 + j * 8 + tc;
            float v0 = acc[i][j][0], v1 = acc[i][j][1];
            float v2 = acc[i][j][2], v3 = acc[i][j][3];
            if (BIAS) {
                const float b0 = bias[col], b1 = bias[col + 1];
                v0 += b0; v1 += b1; v2 += b0; v3 += b1;
            }
            if (LEAKY) {
                v0 = v0 > 0.f ? v0 : 0.01f * v0;
                v1 = v1 > 0.f ? v1 : 0.01f * v1;
                v2 = v2 > 0.f ? v2 : 0.01f * v2;
                v3 = v3 > 0.f ? v3 : 0.01f * v3;
            }
            *(float2*)&C[(size_t)r0 * N + col]       = make_float2(v0, v1);
            *(float2*)&C[(size_t)(r0 + 8) * N + col] = make_float2(v2, v3);
        }
    }
}

// ---------------------------------------------------------------------------
// Fused attention (flash-style online softmax), fp32 — unchanged from R1.
// ---------------------------------------------------------------------------
__global__ void __launch_bounds__(256)
attn_kernel(const float* __restrict__ Q, const float* __restrict__ K,
            const float* __restrict__ V, const int* __restrict__ vl,
            int per_row, float* __restrict__ O)
{
    extern __shared__ __align__(16) float smemf[];
    float (*sQt)[68] = (float(*)[68])(smemf);
    float (*sKt)[68] = (float(*)[68])(smemf + 64 * 68);
    float (*sV )[68] = (float(*)[68])(smemf + 2 * 64 * 68);
    float (*sP )[68] = (float(*)[68])(smemf + 3 * 64 * 68);

    const int tid = threadIdx.x;
    const int bh = blockIdx.x;
    const int b = bh >> 3, h = bh & 7;
    const int q0 = blockIdx.y * 64;
    const int tx = tid & 15, ty = tid >> 4;
    const int tx4 = tx * 4, ty4 = ty * 4;

    const float* Qp = Q + (size_t)(b * T_ + q0) * D_ + h * 64;
    for (int i = tid; i < 64 * 16; i += 256) {
        int r = i >> 4;
        int d4 = (i & 15) * 4;
        float4 v = *(const float4*)(Qp + (size_t)r * D_ + d4);
        sQt[d4 + 0][r] = v.x; sQt[d4 + 1][r] = v.y;
        sQt[d4 + 2][r] = v.z; sQt[d4 + 3][r] = v.w;
    }

    int vlen[4];
#pragma unroll
    for (int ri = 0; ri < 4; ri++)
        vlen[ri] = per_row ? vl[b * T_ + q0 + ty4 + ri] : vl[b];

    float m[4], l[4], acc[4][4];
#pragma unroll
    for (int ri = 0; ri < 4; ri++) {
        m[ri] = -1e30f; l[ri] = 0.f;
#pragma unroll
        for (int cj = 0; cj < 4; cj++) acc[ri][cj] = 0.f;
    }

    for (int k0 = 0; k0 < T_; k0 += 64) {
        __syncthreads();
        const float* Kp = K + (size_t)(b * T_ + k0) * D_ + h * 64;
        const float* Vp = V + (size_t)(b * T_ + k0) * D_ + h * 64;
        for (int i = tid; i < 64 * 16; i += 256) {
            int r = i >> 4;
            int d4 = (i & 15) * 4;
            float4 kv = *(const float4*)(Kp + (size_t)r * D_ + d4);
            sKt[d4 + 0][r] = kv.x; sKt[d4 + 1][r] = kv.y;
            sKt[d4 + 2][r] = kv.z; sKt[d4 + 3][r] = kv.w;
            *(float4*)&sV[r][d4] = *(const float4*)(Vp + (size_t)r * D_ + d4);
        }
        __syncthreads();

        float s[4][4];
#pragma unroll
        for (int ri = 0; ri < 4; ri++)
#pragma unroll
            for (int cj = 0; cj < 4; cj++) s[ri][cj] = 0.f;

#pragma unroll 8
        for (int d = 0; d < 64; d++) {
            float4 qv = *(const float4*)&sQt[d][ty4];
            float4 kv = *(const float4*)&sKt[d][tx4];
            const float qa[4] = {qv.x, qv.y, qv.z, qv.w};
            const float kb[4] = {kv.x, kv.y, kv.z, kv.w};
#pragma unroll
            for (int ri = 0; ri < 4; ri++)
#pragma unroll
                for (int cj = 0; cj < 4; cj++)
                    s[ri][cj] += qa[ri] * kb[cj];
        }

#pragma unroll
        for (int ri = 0; ri < 4; ri++) {
#pragma unroll
            for (int cj = 0; cj < 4; cj++) {
                float sc = s[ri][cj] * 0.125f;
                int kidx = k0 + tx4 + cj;
                s[ri][cj] = (kidx < vlen[ri]) ? sc : -1.0e10f;
            }
            float rm = fmaxf(fmaxf(s[ri][0], s[ri][1]),
                             fmaxf(s[ri][2], s[ri][3]));
#pragma unroll
            for (int off = 8; off; off >>= 1)
                rm = fmaxf(rm, __shfl_xor_sync(0xffffffffu, rm, off));
            float mn = fmaxf(m[ri], rm);
            float alpha = __expf(m[ri] - mn);
            m[ri] = mn;
            float rs = 0.f;
#pragma unroll
            for (int cj = 0; cj < 4; cj++) {
                float p = __expf(s[ri][cj] - mn);
                s[ri][cj] = p;
                rs += p;
            }
#pragma unroll
            for (int off = 8; off; off >>= 1)
                rs += __shfl_xor_sync(0xffffffffu, rs, off);
            l[ri] = l[ri] * alpha + rs;
#pragma unroll
            for (int cj = 0; cj < 4; cj++) acc[ri][cj] *= alpha;
        }

#pragma unroll
        for (int cj = 0; cj < 4; cj++)
            *(float4*)&sP[tx4 + cj][ty4] =
                make_float4(s[0][cj], s[1][cj], s[2][cj], s[3][cj]);
        __syncthreads();

#pragma unroll 8
        for (int k = 0; k < 64; k++) {
            float4 pv = *(const float4*)&sP[k][ty4];
            float4 vv = *(const float4*)&sV[k][tx4];
            const float pa[4] = {pv.x, pv.y, pv.z, pv.w};
            const float vb[4] = {vv.x, vv.y, vv.z, vv.w};
#pragma unroll
            for (int ri = 0; ri < 4; ri++)
#pragma unroll
                for (int cj = 0; cj < 4; cj++)
                    acc[ri][cj] += pa[ri] * vb[cj];
        }
    }

#pragma unroll
    for (int ri = 0; ri < 4; ri++) {
        float inv = 1.0f / l[ri];
        float4 o = make_float4(acc[ri][0] * inv, acc[ri][1] * inv,
                               acc[ri][2] * inv, acc[ri][3] * inv);
        *(float4*)&O[(size_t)(b * T_ + q0 + ty4 + ri) * D_ + h * 64 + tx4] = o;
    }
}

// ---------------------------------------------------------------------------
// out = LayerNorm(A + Bt) * g + be
// ---------------------------------------------------------------------------
__global__ void __launch_bounds__(128)
addnorm_kernel(const float* __restrict__ A, const float* __restrict__ Bt,
               const float* __restrict__ g, const float* __restrict__ be,
               float* __restrict__ out)
{
    const int row = blockIdx.x;
    const int tid = threadIdx.x;
    const size_t base = (size_t)row * D_;

    float4 a = *(const float4*)&A[base + tid * 4];
    float4 b = *(const float4*)&Bt[base + tid * 4];
    float4 x = make_float4(a.x + b.x, a.y + b.y, a.z + b.z, a.w + b.w);

    float s  = x.x + x.y + x.z + x.w;
    float sq = x.x * x.x + x.y * x.y + x.z * x.z + x.w * x.w;
#pragma unroll
    for (int off = 16; off; off >>= 1) {
        s  += __shfl_xor_sync(0xffffffffu, s,  off);
        sq += __shfl_xor_sync(0xffffffffu, sq, off);
    }
    __shared__ float ss[4], ssq[4];
    if ((tid & 31) == 0) { ss[tid >> 5] = s; ssq[tid >> 5] = sq; }
    __syncthreads();
    s  = ss[0] + ss[1] + ss[2] + ss[3];
    sq = ssq[0] + ssq[1] + ssq[2] + ssq[3];

    float mu  = s * (1.0f / D_);
    float var = sq * (1.0f / D_) - mu * mu;
    float inv = rsqrtf(var + 1e-5f);

    float4 gg = *(const float4*)&g[tid * 4];
    float4 bb = *(const float4*)&be[tid * 4];
    float4 o = make_float4((x.x - mu) * inv * gg.x + bb.x,
                           (x.y - mu) * inv * gg.y + bb.y,
                           (x.z - mu) * inv * gg.z + bb.z,
                           (x.w - mu) * inv * gg.w + bb.w);
    *(float4*)&out[base + tid * 4] = o;
}

// ---------------------------------------------------------------------------
// Launch
// ---------------------------------------------------------------------------
extern "C" void kernel_launch(void* const* d_in, const int* in_sizes, int n_in,
                              void* d_out, int out_size)
{
    const float* X    = (const float*)d_in[0];
    const float* ENC  = (const float*)d_in[1];
    const int*   DVL  = (const int*)d_in[2];
    const int*   EVL  = (const int*)d_in[3];
    const float* Wmat[8] = {
        (const float*)d_in[4],  (const float*)d_in[5],
        (const float*)d_in[6],  (const float*)d_in[7],
        (const float*)d_in[8],  (const float*)d_in[9],
        (const float*)d_in[10], (const float*)d_in[11]};
    const float* W1   = (const float*)d_in[12];
    const float* b1   = (const float*)d_in[13];
    const float* W2   = (const float*)d_in[14];
    const float* b2   = (const float*)d_in[15];
    const float* G1   = (const float*)d_in[16];
    const float* BE1  = (const float*)d_in[17];
    const float* G2   = (const float*)d_in[18];
    const float* BE2  = (const float*)d_in[19];
    const float* G3   = (const float*)d_in[20];
    const float* BE3  = (const float*)d_in[21];
    float* out = (float*)d_out;

    float *q, *k, *v, *at, *tmp, *Y, *Z, *ffn;
    __nv_bfloat16 *Ah, *Al, *Bh, *Bl, *Fh, *Fl, *Wh, *Wl;
    cudaGetSymbolAddress((void**)&q,   g_q);
    cudaGetSymbolAddress((void**)&k,   g_k);
    cudaGetSymbolAddress((void**)&v,   g_v);
    cudaGetSymbolAddress((void**)&at,  g_at);
    cudaGetSymbolAddress((void**)&tmp, g_tmp);
    cudaGetSymbolAddress((void**)&Y,   g_Y);
    cudaGetSymbolAddress((void**)&Z,   g_Z);
    cudaGetSymbolAddress((void**)&ffn, g_ffn);
    cudaGetSymbolAddress((void**)&Ah,  g_Ah);
    cudaGetSymbolAddress((void**)&Al,  g_Al);
    cudaGetSymbolAddress((void**)&Bh,  g_Bh);
    cudaGetSymbolAddress((void**)&Bl,  g_Bl);
    cudaGetSymbolAddress((void**)&Fh,  g_Fh);
    cudaGetSymbolAddress((void**)&Fl,  g_Fl);
    cudaGetSymbolAddress((void**)&Wh,  g_Wh);
    cudaGetSymbolAddress((void**)&Wl,  g_Wl);

    const int ATT_SMEM = 4 * 64 * 68 * (int)sizeof(float);
    cudaFuncSetAttribute(attn_kernel,
                         cudaFuncAttributeMaxDynamicSharedMemorySize, ATT_SMEM);
    cudaFuncSetAttribute(gemm_hmma<0, 0>,
                         cudaFuncAttributeMaxDynamicSharedMemorySize, GEMM_SMEM);
    cudaFuncSetAttribute(gemm_hmma<1, 1>,
                         cudaFuncAttributeMaxDynamicSharedMemorySize, GEMM_SMEM);
    cudaFuncSetAttribute(gemm_hmma<1, 0>,
                         cudaFuncAttributeMaxDynamicSharedMemorySize, GEMM_SMEM);

    // weight offsets in Wh/Wl: 8 x DxD, then W1 (FxD), W2 (DxF)
    size_t WO[10];
    for (int i = 0; i < 8; i++) WO[i] = (size_t)i * D_ * D_;
    WO[8] = 8ull * D_ * D_;
    WO[9] = WO[8] + (size_t)F_ * D_;

    dim3 gP (D_ / 128, M_ / 128);   // (4, 128)
    dim3 gF1(F_ / 128, M_ / 128);   // (16, 128)
    dim3 gA (B_ * H_,  T_ / 64);    // (256, 8)

    const int nDD  = D_ * D_ / 4;
    const int nMD  = M_ * D_ / 4;
    const int nFD  = F_ * D_ / 4;
    const int nMF  = M_ * F_ / 4;
    auto blocks = [](int n4) { return (n4 + 255) / 256; };

    // split all weights
    for (int i = 0; i < 8; i++)
        split_kernel<<<blocks(nDD), 256>>>(Wmat[i], Wh + WO[i], Wl + WO[i], nDD);
    split_kernel<<<blocks(nFD), 256>>>(W1, Wh + WO[8], Wl + WO[8], nFD);
    split_kernel<<<blocks(nFD), 256>>>(W2, Wh + WO[9], Wl + WO[9], nFD);

    // ---- self-attention ----
    split_kernel<<<blocks(nMD), 256>>>(X, Ah, Al, nMD);
    gemm_hmma<0, 0><<<gP, 256, GEMM_SMEM>>>(Ah, Al, Wh + WO[0], Wl + WO[0], nullptr, q, D_, D_);
    gemm_hmma<0, 0><<<gP, 256, GEMM_SMEM>>>(Ah, Al, Wh + WO[1], Wl + WO[1], nullptr, k, D_, D_);
    gemm_hmma<0, 0><<<gP, 256, GEMM_SMEM>>>(Ah, Al, Wh + WO[2], Wl + WO[2], nullptr, v, D_, D_);
    attn_kernel<<<gA, 256, ATT_SMEM>>>(q, k, v, DVL, 1, at);
    split_kernel<<<blocks(nMD), 256>>>(at, Bh, Bl, nMD);
    gemm_hmma<0, 0><<<gP, 256, GEMM_SMEM>>>(Bh, Bl, Wh + WO[3], Wl + WO[3], nullptr, tmp, D_, D_);
    addnorm_kernel<<<M_, 128>>>(X, tmp, G1, BE1, Y);

    // ---- cross-attention ----
    split_kernel<<<blocks(nMD), 256>>>(Y, Ah, Al, nMD);
    split_kernel<<<blocks(nMD), 256>>>(ENC, Bh, Bl, nMD);
    gemm_hmma<0, 0><<<gP, 256, GEMM_SMEM>>>(Ah, Al, Wh + WO[4], Wl + WO[4], nullptr, q, D_, D_);
    gemm_hmma<0, 0><<<gP, 256, GEMM_SMEM>>>(Bh, Bl, Wh + WO[5], Wl + WO[5], nullptr, k, D_, D_);
    gemm_hmma<0, 0><<<gP, 256, GEMM_SMEM>>>(Bh, Bl, Wh + WO[6], Wl + WO[6], nullptr, v, D_, D_);
    attn_kernel<<<gA, 256, ATT_SMEM>>>(q, k, v, EVL, 0, at);
    split_kernel<<<blocks(nMD), 256>>>(at, Ah, Al, nMD);
    gemm_hmma<0, 0><<<gP, 256, GEMM_SMEM>>>(Ah, Al, Wh + WO[7], Wl + WO[7], nullptr, tmp, D_, D_);
    addnorm_kernel<<<M_, 128>>>(Y, tmp, G2, BE2, Z);

    // ---- FFN ----
    split_kernel<<<blocks(nMD), 256>>>(Z, Ah, Al, nMD);
    gemm_hmma<1, 1><<<gF1, 256, GEMM_SMEM>>>(Ah, Al, Wh + WO[8], Wl + WO[8], b1, ffn, F_, D_);
    split_kernel<<<blocks(nMF), 256>>>(ffn, Fh, Fl, nMF);
    gemm_hmma<1, 0><<<gP, 256, GEMM_SMEM>>>(Fh, Fl, Wh + WO[9], Wl + WO[9], b2, tmp, D_, F_);
    addnorm_kernel<<<M_, 128>>>(Z, tmp, G3, BE3, out);
}

// round 5
// speedup vs baseline: 2.6969x; 1.4429x over previous
#include <cuda_runtime.h>
#include <cuda_bf16.h>
#include <math.h>
#include <stdint.h>

// Problem constants
#define B_ 32
#define T_ 512
#define D_ 512
#define H_ 8
#define M_ (B_ * T_)   // 16384 rows
#define F_ 2048

// ---------------------------------------------------------------------------
// Scratch (device globals; no allocation allowed)
// ---------------------------------------------------------------------------
__device__ float g_tmp[(size_t)M_ * D_];
__device__ float g_Y  [(size_t)M_ * D_];
__device__ float g_Z  [(size_t)M_ * D_];

__device__ __nv_bfloat16 g_h1 [(size_t)M_ * D_];   // X / Y split hi
__device__ __nv_bfloat16 g_l1 [(size_t)M_ * D_];
__device__ __nv_bfloat16 g_h2 [(size_t)M_ * D_];   // ENC / Z split hi
__device__ __nv_bfloat16 g_l2 [(size_t)M_ * D_];
__device__ __nv_bfloat16 g_qh [(size_t)M_ * D_];
__device__ __nv_bfloat16 g_ql [(size_t)M_ * D_];
__device__ __nv_bfloat16 g_kh [(size_t)M_ * D_];
__device__ __nv_bfloat16 g_kl [(size_t)M_ * D_];
__device__ __nv_bfloat16 g_vh [(size_t)M_ * D_];
__device__ __nv_bfloat16 g_vl [(size_t)M_ * D_];
__device__ __nv_bfloat16 g_ath[(size_t)M_ * D_];
__device__ __nv_bfloat16 g_atl[(size_t)M_ * D_];
__device__ __nv_bfloat16 g_Fh [(size_t)M_ * F_];
__device__ __nv_bfloat16 g_Fl [(size_t)M_ * F_];
__device__ __nv_bfloat16 g_Wh [4194304];
__device__ __nv_bfloat16 g_Wl [4194304];

// ---------------------------------------------------------------------------
// helpers
// ---------------------------------------------------------------------------
__device__ __forceinline__ uint32_t smem_u32(const void* p) {
    uint32_t a;
    asm("{ .reg .u64 t; cvta.to.shared.u64 t, %1; cvt.u32.u64 %0, t; }"
        : "=r"(a) : "l"(p));
    return a;
}

#define CP_ASYNC16(dst, src) \
    asm volatile("cp.async.cg.shared.global [%0], [%1], 16;" :: \
                 "r"(dst), "l"(src) : "memory")
#define CP_COMMIT() asm volatile("cp.async.commit_group;" ::: "memory")
#define CP_WAIT(n)  asm volatile("cp.async.wait_group %0;" :: "n"(n) : "memory")

#define LDMATRIX_X4(r0, r1, r2, r3, addr) \
    asm volatile("ldmatrix.sync.aligned.m8n8.x4.shared.b16 {%0,%1,%2,%3}, [%4];" \
                 : "=r"(r0), "=r"(r1), "=r"(r2), "=r"(r3) : "r"(addr))

#define LDMATRIX_X4_T(r0, r1, r2, r3, addr) \
    asm volatile("ldmatrix.sync.aligned.m8n8.x4.trans.shared.b16 {%0,%1,%2,%3}, [%4];" \
                 : "=r"(r0), "=r"(r1), "=r"(r2), "=r"(r3) : "r"(addr))

#define MMA_BF16(d0, d1, d2, d3, a0, a1, a2, a3, b0, b1) \
    asm volatile("mma.sync.aligned.m16n8k16.row.col.f32.bf16.bf16.f32 " \
                 "{%0,%1,%2,%3}, {%4,%5,%6,%7}, {%8,%9}, {%0,%1,%2,%3};" \
                 : "+f"(d0), "+f"(d1), "+f"(d2), "+f"(d3) \
                 : "r"(a0), "r"(a1), "r"(a2), "r"(a3), "r"(b0), "r"(b1))

__device__ __forceinline__ uint32_t packbf(float x, float y) {
    __nv_bfloat162 t = __floats2bfloat162_rn(x, y);
    return *reinterpret_cast<uint32_t*>(&t);
}
__device__ __forceinline__ void split2(float x, float y, uint32_t& hi, uint32_t& lo) {
    __nv_bfloat162 h = __floats2bfloat162_rn(x, y);
    float hx = __low2float(h), hy = __high2float(h);
    __nv_bfloat162 l = __floats2bfloat162_rn(x - hx, y - hy);
    hi = *reinterpret_cast<uint32_t*>(&h);
    lo = *reinterpret_cast<uint32_t*>(&l);
}

// ---------------------------------------------------------------------------
// split: fp32 -> (bf16 hi, bf16 lo), used for weights, X, ENC
// ---------------------------------------------------------------------------
__global__ void __launch_bounds__(256)
split_kernel(const float* __restrict__ x, __nv_bfloat16* __restrict__ hi,
             __nv_bfloat16* __restrict__ lo, int n4)
{
    int i = blockIdx.x * 256 + threadIdx.x;
    if (i >= n4) return;
    float4 v = ((const float4*)x)[i];
    uint32_t h0, l0, h1, l1;
    split2(v.x, v.y, h0, l0);
    split2(v.z, v.w, h1, l1);
    uint32_t* hp = (uint32_t*)hi;
    uint32_t* lp = (uint32_t*)lo;
    hp[2 * i] = h0; hp[2 * i + 1] = h1;
    lp[2 * i] = l0; lp[2 * i + 1] = l1;
}

// ---------------------------------------------------------------------------
// HMMA GEMM: C[M,N] = (Ah+Al)[M,K] @ (Bh+Bl)[N,K]^T  (3-pass bf16 split)
// SPLIT=1: write bf16 hi/lo instead of fp32.
// ---------------------------------------------------------------------------
#define ROWB 80
#define TILE_B (128 * ROWB)
#define STAGE_B (4 * TILE_B)
#define GEMM_SMEM (2 * STAGE_B)

template <int BIAS, int LEAKY, int SPLIT>
__global__ void __launch_bounds__(256, 2)
gemm_hmma(const __nv_bfloat16* __restrict__ Ah, const __nv_bfloat16* __restrict__ Al,
          const __nv_bfloat16* __restrict__ Bh, const __nv_bfloat16* __restrict__ Bl,
          const float* __restrict__ bias, float* __restrict__ C,
          __nv_bfloat16* __restrict__ Chi, __nv_bfloat16* __restrict__ Clo,
          int N, int K)
{
    extern __shared__ __align__(16) char smem[];
    const uint32_t sbase = smem_u32(smem);

    const int tid = threadIdx.x;
    const int wid = tid >> 5, lane = tid & 31;
    const int wm = wid & 1, wn = wid >> 1;
    const int bm = blockIdx.y * 128;
    const int bn = blockIdx.x * 128;

    const int ldr0 = tid >> 2;
    const int ldc  = (tid & 3) * 8;
    const int ldco = (tid & 3) * 16;

    const __nv_bfloat16* gAh = Ah + (size_t)(bm + ldr0) * K + ldc;
    const __nv_bfloat16* gAl = Al + (size_t)(bm + ldr0) * K + ldc;
    const __nv_bfloat16* gBh = Bh + (size_t)(bn + ldr0) * K + ldc;
    const __nv_bfloat16* gBl = Bl + (size_t)(bn + ldr0) * K + ldc;
    const size_t rstep = (size_t)64 * K;

    const int aRow = lane & 15;
    const int aK8  = (lane >> 4) * 16;
    const int bMat = lane >> 3;
    const int bRow = (lane & 7) + ((bMat >> 1) << 3);
    const int bK8  = (bMat & 1) * 16;

    float acc[4][4][4];
#pragma unroll
    for (int i = 0; i < 4; i++)
#pragma unroll
        for (int j = 0; j < 4; j++)
#pragma unroll
            for (int r = 0; r < 4; r++) acc[i][j][r] = 0.f;

    const int NC = K >> 5;

    auto load_chunk = [&](int c) {
        const uint32_t st = sbase + (c & 1) * STAGE_B;
        const int koff = c << 5;
#pragma unroll
        for (int h = 0; h < 2; h++) {
            const int r = ldr0 + h * 64;
            const uint32_t sro = r * ROWB + ldco;
            CP_ASYNC16(st + sro,              gAh + (size_t)h * rstep + koff);
            CP_ASYNC16(st + TILE_B + sro,     gAl + (size_t)h * rstep + koff);
            CP_ASYNC16(st + 2 * TILE_B + sro, gBh + (size_t)h * rstep + koff);
            CP_ASYNC16(st + 3 * TILE_B + sro, gBl + (size_t)h * rstep + koff);
        }
        CP_COMMIT();
    };

    load_chunk(0);

    for (int c = 0; c < NC; c++) {
        if (c + 1 < NC) { load_chunk(c + 1); CP_WAIT(1); }
        else            { CP_WAIT(0); }
        __syncthreads();

        const uint32_t st = sbase + (c & 1) * STAGE_B;
        const uint32_t sA[2] = { st,              st + TILE_B };
        const uint32_t sB[2] = { st + 2 * TILE_B, st + 3 * TILE_B };

#pragma unroll
        for (int pass = 0; pass < 3; pass++) {
            const uint32_t aB = sA[pass == 2 ? 1 : 0];
            const uint32_t bB = sB[pass == 1 ? 1 : 0];
#pragma unroll
            for (int ks = 0; ks < 2; ks++) {
                uint32_t b[4][2];
#pragma unroll
                for (int j2 = 0; j2 < 2; j2++) {
                    const uint32_t addr = bB +
                        (wn * 32 + j2 * 16 + bRow) * ROWB + ks * 32 + bK8;
                    uint32_t r0, r1, r2, r3;
                    LDMATRIX_X4(r0, r1, r2, r3, addr);
                    b[j2 * 2 + 0][0] = r0; b[j2 * 2 + 0][1] = r1;
                    b[j2 * 2 + 1][0] = r2; b[j2 * 2 + 1][1] = r3;
                }
#pragma unroll
                for (int i = 0; i < 4; i++) {
                    const uint32_t addr = aB +
                        (wm * 64 + i * 16 + aRow) * ROWB + ks * 32 + aK8;
                    uint32_t a0, a1, a2, a3;
                    LDMATRIX_X4(a0, a1, a2, a3, addr);
#pragma unroll
                    for (int j = 0; j < 4; j++)
                        MMA_BF16(acc[i][j][0], acc[i][j][1],
                                 acc[i][j][2], acc[i][j][3],
                                 a0, a1, a2, a3, b[j][0], b[j][1]);
                }
            }
        }
        __syncthreads();
    }

    const int tg = lane >> 2;
    const int tc = (lane & 3) * 2;
#pragma unroll
    for (int i = 0; i < 4; i++) {
        const int r0 = bm + wm * 64 + i * 16 + tg;
#pragma unroll
        for (int j = 0; j < 4; j++) {
            const int col = bn + wn * 32 + j * 8 + tc;
            float v0 = acc[i][j][0], v1 = acc[i][j][1];
            float v2 = acc[i][j][2], v3 = acc[i][j][3];
            if (BIAS) {
                const float b0 = bias[col], b1 = bias[col + 1];
                v0 += b0; v1 += b1; v2 += b0; v3 += b1;
            }
            if (LEAKY) {
                v0 = v0 > 0.f ? v0 : 0.01f * v0;
                v1 = v1 > 0.f ? v1 : 0.01f * v1;
                v2 = v2 > 0.f ? v2 : 0.01f * v2;
                v3 = v3 > 0.f ? v3 : 0.01f * v3;
            }
            if (SPLIT) {
                uint32_t h01, l01, h23, l23;
                split2(v0, v1, h01, l01);
                split2(v2, v3, h23, l23);
                *(uint32_t*)&Chi[(size_t)r0 * N + col]       = h01;
                *(uint32_t*)&Clo[(size_t)r0 * N + col]       = l01;
                *(uint32_t*)&Chi[(size_t)(r0 + 8) * N + col] = h23;
                *(uint32_t*)&Clo[(size_t)(r0 + 8) * N + col] = l23;
            } else {
                *(float2*)&C[(size_t)r0 * N + col]       = make_float2(v0, v1);
                *(float2*)&C[(size_t)(r0 + 8) * N + col] = make_float2(v2, v3);
            }
        }
    }
}

// ---------------------------------------------------------------------------
// HMMA flash attention, split-bf16 (3-pass QK^T, 3-pass PV).
// Grid (B*H, T/128), 256 threads = 8 warps; warp w owns q-rows 16w..16w+15.
// K/V streamed in 64-key tiles, loop bounded by block-max valid_len.
// ---------------------------------------------------------------------------
#define AROWB 144
#define ATT_SMEM (128 * AROWB * 2 + 64 * AROWB * 4)   // Q(h,l) + K(h,l) + V(h,l) = 73728

__global__ void __launch_bounds__(256, 2)
attn_hmma(const __nv_bfloat16* __restrict__ Qh, const __nv_bfloat16* __restrict__ Ql,
          const __nv_bfloat16* __restrict__ Kh, const __nv_bfloat16* __restrict__ Kl,
          const __nv_bfloat16* __restrict__ Vh, const __nv_bfloat16* __restrict__ Vl,
          const int* __restrict__ vlp, int per_row,
          __nv_bfloat16* __restrict__ Oh, __nv_bfloat16* __restrict__ Ol)
{
    extern __shared__ __align__(16) char sm[];
    char* cQh = sm;
    char* cQl = sm + 18432;
    char* cKh = sm + 36864;
    char* cKl = sm + 46080;
    char* cVh = sm + 55296;
    char* cVl = sm + 64512;
    const uint32_t uQh = smem_u32(cQh), uQl = smem_u32(cQl);
    const uint32_t uKh = smem_u32(cKh), uKl = smem_u32(cKl);
    const uint32_t uVh = smem_u32(cVh), uVl = smem_u32(cVl);
    __shared__ int sred[8];

    const int tid = threadIdx.x;
    const int w = tid >> 5, lane = tid & 31;
    const int g = lane >> 2, c = lane & 3;
    const int b = blockIdx.x >> 3, h = blockIdx.x & 7;
    const int q0 = blockIdx.y * 128;

    // block-max valid len -> k-tile loop bound
    int kmax;
    if (per_row) {
        int v = (tid < 128) ? vlp[b * T_ + q0 + tid] : 0;
#pragma unroll
        for (int off = 16; off; off >>= 1)
            v = max(v, __shfl_xor_sync(0xffffffffu, v, off));
        if (lane == 0) sred[w] = v;
        __syncthreads();
        kmax = sred[0];
#pragma unroll
        for (int i = 1; i < 8; i++) kmax = max(kmax, sred[i]);
    } else {
        kmax = vlp[b];
    }
    const int nkt = (kmax + 63) >> 6;

    // load Q tiles (128 rows x 64 d, hi/lo)
    const __nv_bfloat16* qhp = Qh + (size_t)(b * T_ + q0) * D_ + h * 64;
    const __nv_bfloat16* qlp = Ql + (size_t)(b * T_ + q0) * D_ + h * 64;
    for (int i = tid; i < 1024; i += 256) {
        const int r = i >> 3, ch = i & 7;
        const size_t go = (size_t)r * D_ + ch * 8;
        const uint32_t so = r * AROWB + ch * 16;
        *(uint4*)(cQh + so) = *(const uint4*)(qhp + go);
        *(uint4*)(cQl + so) = *(const uint4*)(qlp + go);
    }
    __syncthreads();

    int vl0, vl1;
    if (per_row) {
        vl0 = vlp[b * T_ + q0 + w * 16 + g];
        vl1 = vlp[b * T_ + q0 + w * 16 + g + 8];
    } else {
        vl0 = vl1 = kmax;
    }

    float m0 = -1e30f, m1 = -1e30f, l0 = 0.f, l1 = 0.f;
    float o[8][4];
#pragma unroll
    for (int j = 0; j < 8; j++)
#pragma unroll
        for (int e = 0; e < 4; e++) o[j][e] = 0.f;

    const uint32_t qaddr = (w * 16 + (lane & 15)) * AROWB + (lane >> 4) * 16;
    const int bRow = (lane & 7) + ((lane >> 4) << 3);
    const int bK8  = ((lane >> 3) & 1) * 16;
    const int vRow = (lane & 7) + ((lane >> 3) & 1) * 8;
    const int vColB = (lane >> 4) * 16;

    for (int kt = 0; kt < nkt; kt++) {
        __syncthreads();
        const size_t kb = (size_t)(b * T_ + kt * 64) * D_ + h * 64;
        for (int i = tid; i < 512; i += 256) {
            const int r = i >> 3, ch = i & 7;
            const size_t go = kb + (size_t)r * D_ + ch * 8;
            const uint32_t so = r * AROWB + ch * 16;
            *(uint4*)(cKh + so) = *(const uint4*)(Kh + go);
            *(uint4*)(cKl + so) = *(const uint4*)(Kl + go);
            *(uint4*)(cVh + so) = *(const uint4*)(Vh + go);
            *(uint4*)(cVl + so) = *(const uint4*)(Vl + go);
        }
        __syncthreads();

        // ---- S = Q K^T (3 passes) ----
        float s[8][4];
#pragma unroll
        for (int j = 0; j < 8; j++)
#pragma unroll
            for (int e = 0; e < 4; e++) s[j][e] = 0.f;

#pragma unroll
        for (int kk = 0; kk < 4; kk++) {
            uint32_t ah0, ah1, ah2, ah3, al0, al1, al2, al3;
            LDMATRIX_X4(ah0, ah1, ah2, ah3, uQh + qaddr + kk * 32);
            LDMATRIX_X4(al0, al1, al2, al3, uQl + qaddr + kk * 32);
#pragma unroll
            for (int j2 = 0; j2 < 4; j2++) {
                uint32_t r0, r1, r2, r3;
                LDMATRIX_X4(r0, r1, r2, r3,
                            uKh + (j2 * 16 + bRow) * AROWB + kk * 32 + bK8);
                MMA_BF16(s[2*j2][0], s[2*j2][1], s[2*j2][2], s[2*j2][3],
                         ah0, ah1, ah2, ah3, r0, r1);
                MMA_BF16(s[2*j2+1][0], s[2*j2+1][1], s[2*j2+1][2], s[2*j2+1][3],
                         ah0, ah1, ah2, ah3, r2, r3);
                MMA_BF16(s[2*j2][0], s[2*j2][1], s[2*j2][2], s[2*j2][3],
                         al0, al1, al2, al3, r0, r1);
                MMA_BF16(s[2*j2+1][0], s[2*j2+1][1], s[2*j2+1][2], s[2*j2+1][3],
                         al0, al1, al2, al3, r2, r3);
            }
#pragma unroll
            for (int j2 = 0; j2 < 4; j2++) {
                uint32_t r0, r1, r2, r3;
                LDMATRIX_X4(r0, r1, r2, r3,
                            uKl + (j2 * 16 + bRow) * AROWB + kk * 32 + bK8);
                MMA_BF16(s[2*j2][0], s[2*j2][1], s[2*j2][2], s[2*j2][3],
                         ah0, ah1, ah2, ah3, r0, r1);
                MMA_BF16(s[2*j2+1][0], s[2*j2+1][1], s[2*j2+1][2], s[2*j2+1][3],
                         ah0, ah1, ah2, ah3, r2, r3);
            }
        }

        // ---- online softmax ----
        const int kof = kt * 64 + c * 2;
        float mx0 = -1e30f, mx1 = -1e30f;
#pragma unroll
        for (int j = 0; j < 8; j++) {
            const int ki = kof + j * 8;
            s[j][0] = (ki     < vl0) ? s[j][0] * 0.125f : -1e10f;
            s[j][1] = (ki + 1 < vl0) ? s[j][1] * 0.125f : -1e10f;
            s[j][2] = (ki     < vl1) ? s[j][2] * 0.125f : -1e10f;
            s[j][3] = (ki + 1 < vl1) ? s[j][3] * 0.125f : -1e10f;
            mx0 = fmaxf(mx0, fmaxf(s[j][0], s[j][1]));
            mx1 = fmaxf(mx1, fmaxf(s[j][2], s[j][3]));
        }
        mx0 = fmaxf(mx0, __shfl_xor_sync(0xffffffffu, mx0, 1));
        mx0 = fmaxf(mx0, __shfl_xor_sync(0xffffffffu, mx0, 2));
        mx1 = fmaxf(mx1, __shfl_xor_sync(0xffffffffu, mx1, 1));
        mx1 = fmaxf(mx1, __shfl_xor_sync(0xffffffffu, mx1, 2));

        const float mn0 = fmaxf(m0, mx0), mn1 = fmaxf(m1, mx1);
        const float al_0 = __expf(m0 - mn0), al_1 = __expf(m1 - mn1);
        m0 = mn0; m1 = mn1;

        float rs0 = 0.f, rs1 = 0.f;
#pragma unroll
        for (int j = 0; j < 8; j++) {
            s[j][0] = __expf(s[j][0] - mn0);
            s[j][1] = __expf(s[j][1] - mn0);
            s[j][2] = __expf(s[j][2] - mn1);
            s[j][3] = __expf(s[j][3] - mn1);
            rs0 += s[j][0] + s[j][1];
            rs1 += s[j][2] + s[j][3];
        }
        rs0 += __shfl_xor_sync(0xffffffffu, rs0, 1);
        rs0 += __shfl_xor_sync(0xffffffffu, rs0, 2);
        rs1 += __shfl_xor_sync(0xffffffffu, rs1, 1);
        rs1 += __shfl_xor_sync(0xffffffffu, rs1, 2);
        l0 = l0 * al_0 + rs0;
        l1 = l1 * al_1 + rs1;

#pragma unroll
        for (int j = 0; j < 8; j++) {
            o[j][0] *= al_0; o[j][1] *= al_0;
            o[j][2] *= al_1; o[j][3] *= al_1;
        }

        // ---- O += P V (3 passes, P split in registers) ----
#pragma unroll
        for (int t = 0; t < 4; t++) {
            uint32_t ph[4], pl[4];
            split2(s[2*t][0],   s[2*t][1],   ph[0], pl[0]);
            split2(s[2*t][2],   s[2*t][3],   ph[1], pl[1]);
            split2(s[2*t+1][0], s[2*t+1][1], ph[2], pl[2]);
            split2(s[2*t+1][2], s[2*t+1][3], ph[3], pl[3]);
#pragma unroll
            for (int j2 = 0; j2 < 4; j2++) {
                uint32_t r0, r1, r2, r3;
                LDMATRIX_X4_T(r0, r1, r2, r3,
                              uVh + (t * 16 + vRow) * AROWB + j2 * 32 + vColB);
                MMA_BF16(o[2*j2][0], o[2*j2][1], o[2*j2][2], o[2*j2][3],
                         ph[0], ph[1], ph[2], ph[3], r0, r1);
                MMA_BF16(o[2*j2+1][0], o[2*j2+1][1], o[2*j2+1][2], o[2*j2+1][3],
                         ph[0], ph[1], ph[2], ph[3], r2, r3);
                MMA_BF16(o[2*j2][0], o[2*j2][1], o[2*j2][2], o[2*j2][3],
                         pl[0], pl[1], pl[2], pl[3], r0, r1);
                MMA_BF16(o[2*j2+1][0], o[2*j2+1][1], o[2*j2+1][2], o[2*j2+1][3],
                         pl[0], pl[1], pl[2], pl[3], r2, r3);
            }
#pragma unroll
            for (int j2 = 0; j2 < 4; j2++) {
                uint32_t r0, r1, r2, r3;
                LDMATRIX_X4_T(r0, r1, r2, r3,
                              uVl + (t * 16 + vRow) * AROWB + j2 * 32 + vColB);
                MMA_BF16(o[2*j2][0], o[2*j2][1], o[2*j2][2], o[2*j2][3],
                         ph[0], ph[1], ph[2], ph[3], r0, r1);
                MMA_BF16(o[2*j2+1][0], o[2*j2+1][1], o[2*j2+1][2], o[2*j2+1][3],
                         ph[0], ph[1], ph[2], ph[3], r2, r3);
            }
        }
    }

    // ---- epilogue: normalize, split, store ----
    const float il0 = 1.0f / l0, il1 = 1.0f / l1;
    const int r0g = b * T_ + q0 + w * 16 + g;
    const int r1g = r0g + 8;
#pragma unroll
    for (int j = 0; j < 8; j++) {
        const int col = h * 64 + j * 8 + c * 2;
        uint32_t hi, lo;
        split2(o[j][0] * il0, o[j][1] * il0, hi, lo);
        *(uint32_t*)&Oh[(size_t)r0g * D_ + col] = hi;
        *(uint32_t*)&Ol[(size_t)r0g * D_ + col] = lo;
        split2(o[j][2] * il1, o[j][3] * il1, hi, lo);
        *(uint32_t*)&Oh[(size_t)r1g * D_ + col] = hi;
        *(uint32_t*)&Ol[(size_t)r1g * D_ + col] = lo;
    }
}

// ---------------------------------------------------------------------------
// out = LayerNorm(A + Bt) * g + be ; SPLIT=1 also emits bf16 hi/lo
// ---------------------------------------------------------------------------
template <int SPLIT>
__global__ void __launch_bounds__(128)
addnorm_kernel(const float* __restrict__ A, const float* __restrict__ Bt,
               const float* __restrict__ g, const float* __restrict__ be,
               float* __restrict__ out,
               __nv_bfloat16* __restrict__ ohi, __nv_bfloat16* __restrict__ olo)
{
    const int row = blockIdx.x;
    const int tid = threadIdx.x;
    const size_t base = (size_t)row * D_;

    float4 a = *(const float4*)&A[base + tid * 4];
    float4 b = *(const float4*)&Bt[base + tid * 4];
    float4 x = make_float4(a.x + b.x, a.y + b.y, a.z + b.z, a.w + b.w);

    float s  = x.x + x.y + x.z + x.w;
    float sq = x.x * x.x + x.y * x.y + x.z * x.z + x.w * x.w;
#pragma unroll
    for (int off = 16; off; off >>= 1) {
        s  += __shfl_xor_sync(0xffffffffu, s,  off);
        sq += __shfl_xor_sync(0xffffffffu, sq, off);
    }
    __shared__ float ss[4], ssq[4];
    if ((tid & 31) == 0) { ss[tid >> 5] = s; ssq[tid >> 5] = sq; }
    __syncthreads();
    s  = ss[0] + ss[1] + ss[2] + ss[3];
    sq = ssq[0] + ssq[1] + ssq[2] + ssq[3];

    float mu  = s * (1.0f / D_);
    float var = sq * (1.0f / D_) - mu * mu;
    float inv = rsqrtf(var + 1e-5f);

    float4 gg = *(const float4*)&g[tid * 4];
    float4 bb = *(const float4*)&be[tid * 4];
    float4 oo = make_float4((x.x - mu) * inv * gg.x + bb.x,
                            (x.y - mu) * inv * gg.y + bb.y,
                            (x.z - mu) * inv * gg.z + bb.z,
                            (x.w - mu) * inv * gg.w + bb.w);
    *(float4*)&out[base + tid * 4] = oo;
    if (SPLIT) {
        uint32_t h0, l0, h1, l1;
        split2(oo.x, oo.y, h0, l0);
        split2(oo.z, oo.w, h1, l1);
        uint32_t* hp = (uint32_t*)&ohi[base + tid * 4];
        uint32_t* lp = (uint32_t*)&olo[base + tid * 4];
        hp[0] = h0; hp[1] = h1;
        lp[0] = l0; lp[1] = l1;
    }
}

// ---------------------------------------------------------------------------
// Launch
// ---------------------------------------------------------------------------
extern "C" void kernel_launch(void* const* d_in, const int* in_sizes, int n_in,
                              void* d_out, int out_size)
{
    const float* X    = (const float*)d_in[0];
    const float* ENC  = (const float*)d_in[1];
    const int*   DVL  = (const int*)d_in[2];
    const int*   EVL  = (const int*)d_in[3];
    const float* Wmat[8] = {
        (const float*)d_in[4],  (const float*)d_in[5],
        (const float*)d_in[6],  (const float*)d_in[7],
        (const float*)d_in[8],  (const float*)d_in[9],
        (const float*)d_in[10], (const float*)d_in[11]};
    const float* W1   = (const float*)d_in[12];
    const float* b1   = (const float*)d_in[13];
    const float* W2   = (const float*)d_in[14];
    const float* b2   = (const float*)d_in[15];
    const float* G1   = (const float*)d_in[16];
    const float* BE1  = (const float*)d_in[17];
    const float* G2   = (const float*)d_in[18];
    const float* BE2  = (const float*)d_in[19];
    const float* G3   = (const float*)d_in[20];
    const float* BE3  = (const float*)d_in[21];
    float* out = (float*)d_out;

    float *tmp, *Y, *Z;
    __nv_bfloat16 *h1, *l1, *h2, *l2, *qh, *ql, *kh, *kl, *vh, *vlo;
    __nv_bfloat16 *ath, *atl, *Fh, *Fl, *Wh, *Wl;
    cudaGetSymbolAddress((void**)&tmp, g_tmp);
    cudaGetSymbolAddress((void**)&Y,   g_Y);
    cudaGetSymbolAddress((void**)&Z,   g_Z);
    cudaGetSymbolAddress((void**)&h1,  g_h1);
    cudaGetSymbolAddress((void**)&l1,  g_l1);
    cudaGetSymbolAddress((void**)&h2,  g_h2);
    cudaGetSymbolAddress((void**)&l2,  g_l2);
    cudaGetSymbolAddress((void**)&qh,  g_qh);
    cudaGetSymbolAddress((void**)&ql,  g_ql);
    cudaGetSymbolAddress((void**)&kh,  g_kh);
    cudaGetSymbolAddress((void**)&kl,  g_kl);
    cudaGetSymbolAddress((void**)&vh,  g_vh);
    cudaGetSymbolAddress((void**)&vlo, g_vl);
    cudaGetSymbolAddress((void**)&ath, g_ath);
    cudaGetSymbolAddress((void**)&atl, g_atl);
    cudaGetSymbolAddress((void**)&Fh,  g_Fh);
    cudaGetSymbolAddress((void**)&Fl,  g_Fl);
    cudaGetSymbolAddress((void**)&Wh,  g_Wh);
    cudaGetSymbolAddress((void**)&Wl,  g_Wl);

    cudaFuncSetAttribute(attn_hmma,
                         cudaFuncAttributeMaxDynamicSharedMemorySize, ATT_SMEM);
    cudaFuncSetAttribute(gemm_hmma<0, 0, 1>,
                         cudaFuncAttributeMaxDynamicSharedMemorySize, GEMM_SMEM);
    cudaFuncSetAttribute(gemm_hmma<0, 0, 0>,
                         cudaFuncAttributeMaxDynamicSharedMemorySize, GEMM_SMEM);
    cudaFuncSetAttribute(gemm_hmma<1, 1, 1>,
                         cudaFuncAttributeMaxDynamicSharedMemorySize, GEMM_SMEM);
    cudaFuncSetAttribute(gemm_hmma<1, 0, 0>,
                         cudaFuncAttributeMaxDynamicSharedMemorySize, GEMM_SMEM);

    size_t WO[10];
    for (int i = 0; i < 8; i++) WO[i] = (size_t)i * D_ * D_;
    WO[8] = 8ull * D_ * D_;
    WO[9] = WO[8] + (size_t)F_ * D_;

    dim3 gP (D_ / 128, M_ / 128);
    dim3 gF1(F_ / 128, M_ / 128);
    dim3 gA (B_ * H_,  T_ / 128);

    const int nDD = D_ * D_ / 4;
    const int nMD = M_ * D_ / 4;
    const int nFD = F_ * D_ / 4;
    auto blocks = [](int n4) { return (n4 + 255) / 256; };

    // weight + input splits
    for (int i = 0; i < 8; i++)
        split_kernel<<<blocks(nDD), 256>>>(Wmat[i], Wh + WO[i], Wl + WO[i], nDD);
    split_kernel<<<blocks(nFD), 256>>>(W1, Wh + WO[8], Wl + WO[8], nFD);
    split_kernel<<<blocks(nFD), 256>>>(W2, Wh + WO[9], Wl + WO[9], nFD);
    split_kernel<<<blocks(nMD), 256>>>(X,   h1, l1, nMD);
    split_kernel<<<blocks(nMD), 256>>>(ENC, h2, l2, nMD);

    // ---- self-attention ----
    gemm_hmma<0,0,1><<<gP, 256, GEMM_SMEM>>>(h1, l1, Wh+WO[0], Wl+WO[0], nullptr, nullptr, qh, ql, D_, D_);
    gemm_hmma<0,0,1><<<gP, 256, GEMM_SMEM>>>(h1, l1, Wh+WO[1], Wl+WO[1], nullptr, nullptr, kh, kl, D_, D_);
    gemm_hmma<0,0,1><<<gP, 256, GEMM_SMEM>>>(h1, l1, Wh+WO[2], Wl+WO[2], nullptr, nullptr, vh, vlo, D_, D_);
    attn_hmma<<<gA, 256, ATT_SMEM>>>(qh, ql, kh, kl, vh, vlo, DVL, 1, ath, atl);
    gemm_hmma<0,0,0><<<gP, 256, GEMM_SMEM>>>(ath, atl, Wh+WO[3], Wl+WO[3], nullptr, tmp, nullptr, nullptr, D_, D_);
    addnorm_kernel<1><<<M_, 128>>>(X, tmp, G1, BE1, Y, h1, l1);

    // ---- cross-attention ----
    gemm_hmma<0,0,1><<<gP, 256, GEMM_SMEM>>>(h1, l1, Wh+WO[4], Wl+WO[4], nullptr, nullptr, qh, ql, D_, D_);
    gemm_hmma<0,0,1><<<gP, 256, GEMM_SMEM>>>(h2, l2, Wh+WO[5], Wl+WO[5], nullptr, nullptr, kh, kl, D_, D_);
    gemm_hmma<0,0,1><<<gP, 256, GEMM_SMEM>>>(h2, l2, Wh+WO[6], Wl+WO[6], nullptr, nullptr, vh, vlo, D_, D_);
    attn_hmma<<<gA, 256, ATT_SMEM>>>(qh, ql, kh, kl, vh, vlo, EVL, 0, ath, atl);
    gemm_hmma<0,0,0><<<gP, 256, GEMM_SMEM>>>(ath, atl, Wh+WO[7], Wl+WO[7], nullptr, tmp, nullptr, nullptr, D_, D_);
    addnorm_kernel<1><<<M_, 128>>>(Y, tmp, G2, BE2, Z, h2, l2);

    // ---- FFN ----
    gemm_hmma<1,1,1><<<gF1, 256, GEMM_SMEM>>>(h2, l2, Wh+WO[8], Wl+WO[8], b1, nullptr, Fh, Fl, F_, D_);
    gemm_hmma<1,0,0><<<gP, 256, GEMM_SMEM>>>(Fh, Fl, Wh+WO[9], Wl+WO[9], b2, tmp, nullptr, nullptr, D_, F_);
    addnorm_kernel<0><<<M_, 128>>>(Z, tmp, G3, BE3, out, nullptr, nullptr);
}

// round 6
// speedup vs baseline: 2.8266x; 1.0481x over previous
#include <cuda_runtime.h>
#include <cuda_bf16.h>
#include <math.h>
#include <stdint.h>

// Problem constants
#define B_ 32
#define T_ 512
#define D_ 512
#define H_ 8
#define M_ (B_ * T_)   // 16384 rows
#define F_ 2048

// ---------------------------------------------------------------------------
// Scratch (device globals; no allocation allowed)
// ---------------------------------------------------------------------------
__device__ float g_tmp[(size_t)M_ * D_];
__device__ float g_Y  [(size_t)M_ * D_];
__device__ float g_Z  [(size_t)M_ * D_];

__device__ __nv_bfloat16 g_h1  [(size_t)M_ * D_];     // X / Y split
__device__ __nv_bfloat16 g_l1  [(size_t)M_ * D_];
__device__ __nv_bfloat16 g_h2  [(size_t)M_ * D_];     // ENC / Z split
__device__ __nv_bfloat16 g_l2  [(size_t)M_ * D_];
__device__ __nv_bfloat16 g_qkvh[(size_t)M_ * 1536];   // self QKV fused
__device__ __nv_bfloat16 g_qkvl[(size_t)M_ * 1536];
__device__ __nv_bfloat16 g_kvh [(size_t)M_ * 1024];   // cross KV fused
__device__ __nv_bfloat16 g_kvl [(size_t)M_ * 1024];
__device__ __nv_bfloat16 g_q2h [(size_t)M_ * D_];     // cross Q
__device__ __nv_bfloat16 g_q2l [(size_t)M_ * D_];
__device__ __nv_bfloat16 g_ath [(size_t)M_ * D_];
__device__ __nv_bfloat16 g_atl [(size_t)M_ * D_];
__device__ __nv_bfloat16 g_Fh  [(size_t)M_ * F_];
__device__ __nv_bfloat16 g_Fl  [(size_t)M_ * F_];
__device__ __nv_bfloat16 g_Wh  [4194304];
__device__ __nv_bfloat16 g_Wl  [4194304];

// ---------------------------------------------------------------------------
// helpers
// ---------------------------------------------------------------------------
__device__ __forceinline__ uint32_t smem_u32(const void* p) {
    uint32_t a;
    asm("{ .reg .u64 t; cvta.to.shared.u64 t, %1; cvt.u32.u64 %0, t; }"
        : "=r"(a) : "l"(p));
    return a;
}

#define CP_ASYNC16(dst, src) \
    asm volatile("cp.async.cg.shared.global [%0], [%1], 16;" :: \
                 "r"(dst), "l"(src) : "memory")
#define CP_COMMIT() asm volatile("cp.async.commit_group;" ::: "memory")
#define CP_WAIT(n)  asm volatile("cp.async.wait_group %0;" :: "n"(n) : "memory")

#define LDMATRIX_X4(r0, r1, r2, r3, addr) \
    asm volatile("ldmatrix.sync.aligned.m8n8.x4.shared.b16 {%0,%1,%2,%3}, [%4];" \
                 : "=r"(r0), "=r"(r1), "=r"(r2), "=r"(r3) : "r"(addr))

#define LDMATRIX_X4_T(r0, r1, r2, r3, addr) \
    asm volatile("ldmatrix.sync.aligned.m8n8.x4.trans.shared.b16 {%0,%1,%2,%3}, [%4];" \
                 : "=r"(r0), "=r"(r1), "=r"(r2), "=r"(r3) : "r"(addr))

#define MMA_BF16(d0, d1, d2, d3, a0, a1, a2, a3, b0, b1) \
    asm volatile("mma.sync.aligned.m16n8k16.row.col.f32.bf16.bf16.f32 " \
                 "{%0,%1,%2,%3}, {%4,%5,%6,%7}, {%8,%9}, {%0,%1,%2,%3};" \
                 : "+f"(d0), "+f"(d1), "+f"(d2), "+f"(d3) \
                 : "r"(a0), "r"(a1), "r"(a2), "r"(a3), "r"(b0), "r"(b1))

__device__ __forceinline__ void split2(float x, float y, uint32_t& hi, uint32_t& lo) {
    __nv_bfloat162 h = __floats2bfloat162_rn(x, y);
    float hx = __low2float(h), hy = __high2float(h);
    __nv_bfloat162 l = __floats2bfloat162_rn(x - hx, y - hy);
    hi = *reinterpret_cast<uint32_t*>(&h);
    lo = *reinterpret_cast<uint32_t*>(&l);
}

// ---------------------------------------------------------------------------
// merged split: 12 segments in one launch
// ---------------------------------------------------------------------------
struct SplitSegs {
    const float* src[12];
    __nv_bfloat16* hi[12];
    __nv_bfloat16* lo[12];
    int n4[12];
};

__global__ void __launch_bounds__(256)
msplit_kernel(SplitSegs s)
{
    int i = blockIdx.x * 256 + threadIdx.x;
#pragma unroll
    for (int k = 0; k < 12; k++) {
        if (i < s.n4[k]) {
            float4 v = ((const float4*)s.src[k])[i];
            uint32_t h0, l0, h1, l1;
            split2(v.x, v.y, h0, l0);
            split2(v.z, v.w, h1, l1);
            uint32_t* hp = (uint32_t*)s.hi[k];
            uint32_t* lp = (uint32_t*)s.lo[k];
            hp[2 * i] = h0; hp[2 * i + 1] = h1;
            lp[2 * i] = l0; lp[2 * i + 1] = l1;
            return;
        }
        i -= s.n4[k];
    }
}

// ---------------------------------------------------------------------------
// HMMA GEMM: C[M,N] = (Ah+Al)[M,K] @ (Bh+Bl)[N,K]^T  (3-pass bf16 split)
// Restructured inner loop: per k-slice load Ah,Bh,Bl frags once, run
// Ah*Bh + Ah*Bl, then overwrite A regs with Al for Al*Bh.
// ---------------------------------------------------------------------------
#define ROWB 80
#define TILE_B (128 * ROWB)
#define STAGE_B (4 * TILE_B)
#define GEMM_SMEM (2 * STAGE_B)

template <int BIAS, int LEAKY, int SPLIT>
__global__ void __launch_bounds__(256, 2)
gemm_hmma(const __nv_bfloat16* __restrict__ Ah, const __nv_bfloat16* __restrict__ Al,
          const __nv_bfloat16* __restrict__ Bh, const __nv_bfloat16* __restrict__ Bl,
          const float* __restrict__ bias, float* __restrict__ C,
          __nv_bfloat16* __restrict__ Chi, __nv_bfloat16* __restrict__ Clo,
          int N, int K)
{
    extern __shared__ __align__(16) char smem[];
    const uint32_t sbase = smem_u32(smem);

    const int tid = threadIdx.x;
    const int wid = tid >> 5, lane = tid & 31;
    const int wm = wid & 1, wn = wid >> 1;
    const int bm = blockIdx.y * 128;
    const int bn = blockIdx.x * 128;

    const int ldr0 = tid >> 2;
    const int ldc  = (tid & 3) * 8;
    const int ldco = (tid & 3) * 16;

    const __nv_bfloat16* gAh = Ah + (size_t)(bm + ldr0) * K + ldc;
    const __nv_bfloat16* gAl = Al + (size_t)(bm + ldr0) * K + ldc;
    const __nv_bfloat16* gBh = Bh + (size_t)(bn + ldr0) * K + ldc;
    const __nv_bfloat16* gBl = Bl + (size_t)(bn + ldr0) * K + ldc;
    const size_t rstep = (size_t)64 * K;

    const int aRow = lane & 15;
    const int aK8  = (lane >> 4) * 16;
    const int bMat = lane >> 3;
    const int bRow = (lane & 7) + ((bMat >> 1) << 3);
    const int bK8  = (bMat & 1) * 16;

    float acc[4][4][4];
#pragma unroll
    for (int i = 0; i < 4; i++)
#pragma unroll
        for (int j = 0; j < 4; j++)
#pragma unroll
            for (int r = 0; r < 4; r++) acc[i][j][r] = 0.f;

    const int NC = K >> 5;

    auto load_chunk = [&](int c) {
        const uint32_t st = sbase + (c & 1) * STAGE_B;
        const int koff = c << 5;
#pragma unroll
        for (int h = 0; h < 2; h++) {
            const int r = ldr0 + h * 64;
            const uint32_t sro = r * ROWB + ldco;
            CP_ASYNC16(st + sro,              gAh + (size_t)h * rstep + koff);
            CP_ASYNC16(st + TILE_B + sro,     gAl + (size_t)h * rstep + koff);
            CP_ASYNC16(st + 2 * TILE_B + sro, gBh + (size_t)h * rstep + koff);
            CP_ASYNC16(st + 3 * TILE_B + sro, gBl + (size_t)h * rstep + koff);
        }
        CP_COMMIT();
    };

    load_chunk(0);

    for (int c = 0; c < NC; c++) {
        if (c + 1 < NC) { load_chunk(c + 1); CP_WAIT(1); }
        else            { CP_WAIT(0); }
        __syncthreads();

        const uint32_t st  = sbase + (c & 1) * STAGE_B;
        const uint32_t aBh = st,              aBl = st + TILE_B;
        const uint32_t bBh = st + 2 * TILE_B, bBl = st + 3 * TILE_B;

#pragma unroll
        for (int ks = 0; ks < 2; ks++) {
            // B frags: hi and lo (4x ldmatrix.x4)
            uint32_t bh[4][2], bl[4][2];
#pragma unroll
            for (int j2 = 0; j2 < 2; j2++) {
                const uint32_t off = (wn * 32 + j2 * 16 + bRow) * ROWB + ks * 32 + bK8;
                uint32_t r0, r1, r2, r3;
                LDMATRIX_X4(r0, r1, r2, r3, bBh + off);
                bh[j2 * 2 + 0][0] = r0; bh[j2 * 2 + 0][1] = r1;
                bh[j2 * 2 + 1][0] = r2; bh[j2 * 2 + 1][1] = r3;
                LDMATRIX_X4(r0, r1, r2, r3, bBl + off);
                bl[j2 * 2 + 0][0] = r0; bl[j2 * 2 + 0][1] = r1;
                bl[j2 * 2 + 1][0] = r2; bl[j2 * 2 + 1][1] = r3;
            }
            // A hi frags, pass0 (Ah*Bh) + pass1 (Ah*Bl)
            uint32_t a[4][4];
#pragma unroll
            for (int i = 0; i < 4; i++) {
                const uint32_t off = (wm * 64 + i * 16 + aRow) * ROWB + ks * 32 + aK8;
                LDMATRIX_X4(a[i][0], a[i][1], a[i][2], a[i][3], aBh + off);
            }
#pragma unroll
            for (int i = 0; i < 4; i++)
#pragma unroll
                for (int j = 0; j < 4; j++)
                    MMA_BF16(acc[i][j][0], acc[i][j][1], acc[i][j][2], acc[i][j][3],
                             a[i][0], a[i][1], a[i][2], a[i][3], bh[j][0], bh[j][1]);
#pragma unroll
            for (int i = 0; i < 4; i++)
#pragma unroll
                for (int j = 0; j < 4; j++)
                    MMA_BF16(acc[i][j][0], acc[i][j][1], acc[i][j][2], acc[i][j][3],
                             a[i][0], a[i][1], a[i][2], a[i][3], bl[j][0], bl[j][1]);
            // A lo frags (reuse regs), pass2 (Al*Bh)
#pragma unroll
            for (int i = 0; i < 4; i++) {
                const uint32_t off = (wm * 64 + i * 16 + aRow) * ROWB + ks * 32 + aK8;
                LDMATRIX_X4(a[i][0], a[i][1], a[i][2], a[i][3], aBl + off);
            }
#pragma unroll
            for (int i = 0; i < 4; i++)
#pragma unroll
                for (int j = 0; j < 4; j++)
                    MMA_BF16(acc[i][j][0], acc[i][j][1], acc[i][j][2], acc[i][j][3],
                             a[i][0], a[i][1], a[i][2], a[i][3], bh[j][0], bh[j][1]);
        }
        __syncthreads();
    }

    const int tg = lane >> 2;
    const int tc = (lane & 3) * 2;
#pragma unroll
    for (int i = 0; i < 4; i++) {
        const int r0 = bm + wm * 64 + i * 16 + tg;
#pragma unroll
        for (int j = 0; j < 4; j++) {
            const int col = bn + wn * 32 + j * 8 + tc;
            float v0 = acc[i][j][0], v1 = acc[i][j][1];
            float v2 = acc[i][j][2], v3 = acc[i][j][3];
            if (BIAS) {
                const float b0 = bias[col], b1 = bias[col + 1];
                v0 += b0; v1 += b1; v2 += b0; v3 += b1;
            }
            if (LEAKY) {
                v0 = v0 > 0.f ? v0 : 0.01f * v0;
                v1 = v1 > 0.f ? v1 : 0.01f * v1;
                v2 = v2 > 0.f ? v2 : 0.01f * v2;
                v3 = v3 > 0.f ? v3 : 0.01f * v3;
            }
            if (SPLIT) {
                uint32_t h01, l01, h23, l23;
                split2(v0, v1, h01, l01);
                split2(v2, v3, h23, l23);
                *(uint32_t*)&Chi[(size_t)r0 * N + col]       = h01;
                *(uint32_t*)&Clo[(size_t)r0 * N + col]       = l01;
                *(uint32_t*)&Chi[(size_t)(r0 + 8) * N + col] = h23;
                *(uint32_t*)&Clo[(size_t)(r0 + 8) * N + col] = l23;
            } else {
                *(float2*)&C[(size_t)r0 * N + col]       = make_float2(v0, v1);
                *(float2*)&C[(size_t)(r0 + 8) * N + col] = make_float2(v2, v3);
            }
        }
    }
}

// ---------------------------------------------------------------------------
// HMMA flash attention, split-bf16; Q/KV row strides are parameters so the
// fused QKV / KV projection buffers can be consumed in place.
// ---------------------------------------------------------------------------
#define AROWB 144
#define ATT_SMEM (128 * AROWB * 2 + 64 * AROWB * 4)   // 73728

__global__ void __launch_bounds__(256, 2)
attn_hmma(const __nv_bfloat16* __restrict__ Qh, const __nv_bfloat16* __restrict__ Ql,
          int qs,
          const __nv_bfloat16* __restrict__ Kh, const __nv_bfloat16* __restrict__ Kl,
          const __nv_bfloat16* __restrict__ Vh, const __nv_bfloat16* __restrict__ Vl,
          int kvs,
          const int* __restrict__ vlp, int per_row,
          __nv_bfloat16* __restrict__ Oh, __nv_bfloat16* __restrict__ Ol)
{
    extern __shared__ __align__(16) char sm[];
    char* cQh = sm;
    char* cQl = sm + 18432;
    char* cKh = sm + 36864;
    char* cKl = sm + 46080;
    char* cVh = sm + 55296;
    char* cVl = sm + 64512;
    const uint32_t uQh = smem_u32(cQh), uQl = smem_u32(cQl);
    const uint32_t uKh = smem_u32(cKh), uKl = smem_u32(cKl);
    const uint32_t uVh = smem_u32(cVh), uVl = smem_u32(cVl);
    __shared__ int sred[8];

    const int tid = threadIdx.x;
    const int w = tid >> 5, lane = tid & 31;
    const int g = lane >> 2, c = lane & 3;
    const int b = blockIdx.x >> 3, h = blockIdx.x & 7;
    const int q0 = blockIdx.y * 128;

    int kmax;
    if (per_row) {
        int v = (tid < 128) ? vlp[b * T_ + q0 + tid] : 0;
#pragma unroll
        for (int off = 16; off; off >>= 1)
            v = max(v, __shfl_xor_sync(0xffffffffu, v, off));
        if (lane == 0) sred[w] = v;
        __syncthreads();
        kmax = sred[0];
#pragma unroll
        for (int i = 1; i < 8; i++) kmax = max(kmax, sred[i]);
    } else {
        kmax = vlp[b];
    }
    const int nkt = (kmax + 63) >> 6;

    const __nv_bfloat16* qhp = Qh + (size_t)(b * T_ + q0) * qs + h * 64;
    const __nv_bfloat16* qlp = Ql + (size_t)(b * T_ + q0) * qs + h * 64;
    for (int i = tid; i < 1024; i += 256) {
        const int r = i >> 3, ch = i & 7;
        const size_t go = (size_t)r * qs + ch * 8;
        const uint32_t so = r * AROWB + ch * 16;
        *(uint4*)(cQh + so) = *(const uint4*)(qhp + go);
        *(uint4*)(cQl + so) = *(const uint4*)(qlp + go);
    }
    __syncthreads();

    int vl0, vl1;
    if (per_row) {
        vl0 = vlp[b * T_ + q0 + w * 16 + g];
        vl1 = vlp[b * T_ + q0 + w * 16 + g + 8];
    } else {
        vl0 = vl1 = kmax;
    }

    float m0 = -1e30f, m1 = -1e30f, l0 = 0.f, l1 = 0.f;
    float o[8][4];
#pragma unroll
    for (int j = 0; j < 8; j++)
#pragma unroll
        for (int e = 0; e < 4; e++) o[j][e] = 0.f;

    const uint32_t qaddr = (w * 16 + (lane & 15)) * AROWB + (lane >> 4) * 16;
    const int bRow = (lane & 7) + ((lane >> 4) << 3);
    const int bK8  = ((lane >> 3) & 1) * 16;
    const int vRow = (lane & 7) + ((lane >> 3) & 1) * 8;
    const int vColB = (lane >> 4) * 16;

    for (int kt = 0; kt < nkt; kt++) {
        __syncthreads();
        const size_t kb = (size_t)(b * T_ + kt * 64) * kvs + h * 64;
        for (int i = tid; i < 512; i += 256) {
            const int r = i >> 3, ch = i & 7;
            const size_t go = kb + (size_t)r * kvs + ch * 8;
            const uint32_t so = r * AROWB + ch * 16;
            *(uint4*)(cKh + so) = *(const uint4*)(Kh + go);
            *(uint4*)(cKl + so) = *(const uint4*)(Kl + go);
            *(uint4*)(cVh + so) = *(const uint4*)(Vh + go);
            *(uint4*)(cVl + so) = *(const uint4*)(Vl + go);
        }
        __syncthreads();

        float s[8][4];
#pragma unroll
        for (int j = 0; j < 8; j++)
#pragma unroll
            for (int e = 0; e < 4; e++) s[j][e] = 0.f;

#pragma unroll
        for (int kk = 0; kk < 4; kk++) {
            uint32_t ah0, ah1, ah2, ah3, al0, al1, al2, al3;
            LDMATRIX_X4(ah0, ah1, ah2, ah3, uQh + qaddr + kk * 32);
            LDMATRIX_X4(al0, al1, al2, al3, uQl + qaddr + kk * 32);
#pragma unroll
            for (int j2 = 0; j2 < 4; j2++) {
                uint32_t r0, r1, r2, r3;
                LDMATRIX_X4(r0, r1, r2, r3,
                            uKh + (j2 * 16 + bRow) * AROWB + kk * 32 + bK8);
                MMA_BF16(s[2*j2][0], s[2*j2][1], s[2*j2][2], s[2*j2][3],
                         ah0, ah1, ah2, ah3, r0, r1);
                MMA_BF16(s[2*j2+1][0], s[2*j2+1][1], s[2*j2+1][2], s[2*j2+1][3],
                         ah0, ah1, ah2, ah3, r2, r3);
                MMA_BF16(s[2*j2][0], s[2*j2][1], s[2*j2][2], s[2*j2][3],
                         al0, al1, al2, al3, r0, r1);
                MMA_BF16(s[2*j2+1][0], s[2*j2+1][1], s[2*j2+1][2], s[2*j2+1][3],
                         al0, al1, al2, al3, r2, r3);
            }
#pragma unroll
            for (int j2 = 0; j2 < 4; j2++) {
                uint32_t r0, r1, r2, r3;
                LDMATRIX_X4(r0, r1, r2, r3,
                            uKl + (j2 * 16 + bRow) * AROWB + kk * 32 + bK8);
                MMA_BF16(s[2*j2][0], s[2*j2][1], s[2*j2][2], s[2*j2][3],
                         ah0, ah1, ah2, ah3, r0, r1);
                MMA_BF16(s[2*j2+1][0], s[2*j2+1][1], s[2*j2+1][2], s[2*j2+1][3],
                         ah0, ah1, ah2, ah3, r2, r3);
            }
        }

        const int kof = kt * 64 + c * 2;
        float mx0 = -1e30f, mx1 = -1e30f;
#pragma unroll
        for (int j = 0; j < 8; j++) {
            const int ki = kof + j * 8;
            s[j][0] = (ki     < vl0) ? s[j][0] * 0.125f : -1e10f;
            s[j][1] = (ki + 1 < vl0) ? s[j][1] * 0.125f : -1e10f;
            s[j][2] = (ki     < vl1) ? s[j][2] * 0.125f : -1e10f;
            s[j][3] = (ki + 1 < vl1) ? s[j][3] * 0.125f : -1e10f;
            mx0 = fmaxf(mx0, fmaxf(s[j][0], s[j][1]));
            mx1 = fmaxf(mx1, fmaxf(s[j][2], s[j][3]));
        }
        mx0 = fmaxf(mx0, __shfl_xor_sync(0xffffffffu, mx0, 1));
        mx0 = fmaxf(mx0, __shfl_xor_sync(0xffffffffu, mx0, 2));
        mx1 = fmaxf(mx1, __shfl_xor_sync(0xffffffffu, mx1, 1));
        mx1 = fmaxf(mx1, __shfl_xor_sync(0xffffffffu, mx1, 2));

        const float mn0 = fmaxf(m0, mx0), mn1 = fmaxf(m1, mx1);
        const float al_0 = __expf(m0 - mn0), al_1 = __expf(m1 - mn1);
        m0 = mn0; m1 = mn1;

        float rs0 = 0.f, rs1 = 0.f;
#pragma unroll
        for (int j = 0; j < 8; j++) {
            s[j][0] = __expf(s[j][0] - mn0);
            s[j][1] = __expf(s[j][1] - mn0);
            s[j][2] = __expf(s[j][2] - mn1);
            s[j][3] = __expf(s[j][3] - mn1);
            rs0 += s[j][0] + s[j][1];
            rs1 += s[j][2] + s[j][3];
        }
        rs0 += __shfl_xor_sync(0xffffffffu, rs0, 1);
        rs0 += __shfl_xor_sync(0xffffffffu, rs0, 2);
        rs1 += __shfl_xor_sync(0xffffffffu, rs1, 1);
        rs1 += __shfl_xor_sync(0xffffffffu, rs1, 2);
        l0 = l0 * al_0 + rs0;
        l1 = l1 * al_1 + rs1;

#pragma unroll
        for (int j = 0; j < 8; j++) {
            o[j][0] *= al_0; o[j][1] *= al_0;
            o[j][2] *= al_1; o[j][3] *= al_1;
        }

#pragma unroll
        for (int t = 0; t < 4; t++) {
            uint32_t ph[4], pl[4];
            split2(s[2*t][0],   s[2*t][1],   ph[0], pl[0]);
            split2(s[2*t][2],   s[2*t][3],   ph[1], pl[1]);
            split2(s[2*t+1][0], s[2*t+1][1], ph[2], pl[2]);
            split2(s[2*t+1][2], s[2*t+1][3], ph[3], pl[3]);
#pragma unroll
            for (int j2 = 0; j2 < 4; j2++) {
                uint32_t r0, r1, r2, r3;
                LDMATRIX_X4_T(r0, r1, r2, r3,
                              uVh + (t * 16 + vRow) * AROWB + j2 * 32 + vColB);
                MMA_BF16(o[2*j2][0], o[2*j2][1], o[2*j2][2], o[2*j2][3],
                         ph[0], ph[1], ph[2], ph[3], r0, r1);
                MMA_BF16(o[2*j2+1][0], o[2*j2+1][1], o[2*j2+1][2], o[2*j2+1][3],
                         ph[0], ph[1], ph[2], ph[3], r2, r3);
                MMA_BF16(o[2*j2][0], o[2*j2][1], o[2*j2][2], o[2*j2][3],
                         pl[0], pl[1], pl[2], pl[3], r0, r1);
                MMA_BF16(o[2*j2+1][0], o[2*j2+1][1], o[2*j2+1][2], o[2*j2+1][3],
                         pl[0], pl[1], pl[2], pl[3], r2, r3);
            }
#pragma unroll
            for (int j2 = 0; j2 < 4; j2++) {
                uint32_t r0, r1, r2, r3;
                LDMATRIX_X4_T(r0, r1, r2, r3,
                              uVl + (t * 16 + vRow) * AROWB + j2 * 32 + vColB);
                MMA_BF16(o[2*j2][0], o[2*j2][1], o[2*j2][2], o[2*j2][3],
                         ph[0], ph[1], ph[2], ph[3], r0, r1);
                MMA_BF16(o[2*j2+1][0], o[2*j2+1][1], o[2*j2+1][2], o[2*j2+1][3],
                         ph[0], ph[1], ph[2], ph[3], r2, r3);
            }
        }
    }

    const float il0 = 1.0f / l0, il1 = 1.0f / l1;
    const int r0g = b * T_ + q0 + w * 16 + g;
    const int r1g = r0g + 8;
#pragma unroll
    for (int j = 0; j < 8; j++) {
        const int col = h * 64 + j * 8 + c * 2;
        uint32_t hi, lo;
        split2(o[j][0] * il0, o[j][1] * il0, hi, lo);
        *(uint32_t*)&Oh[(size_t)r0g * D_ + col] = hi;
        *(uint32_t*)&Ol[(size_t)r0g * D_ + col] = lo;
        split2(o[j][2] * il1, o[j][3] * il1, hi, lo);
        *(uint32_t*)&Oh[(size_t)r1g * D_ + col] = hi;
        *(uint32_t*)&Ol[(size_t)r1g * D_ + col] = lo;
    }
}

// ---------------------------------------------------------------------------
// out = LayerNorm(A + Bt) * g + be ; SPLIT=1 also emits bf16 hi/lo
// ---------------------------------------------------------------------------
template <int SPLIT>
__global__ void __launch_bounds__(128)
addnorm_kernel(const float* __restrict__ A, const float* __restrict__ Bt,
               const float* __restrict__ g, const float* __restrict__ be,
               float* __restrict__ out,
               __nv_bfloat16* __restrict__ ohi, __nv_bfloat16* __restrict__ olo)
{
    const int row = blockIdx.x;
    const int tid = threadIdx.x;
    const size_t base = (size_t)row * D_;

    float4 a = *(const float4*)&A[base + tid * 4];
    float4 b = *(const float4*)&Bt[base + tid * 4];
    float4 x = make_float4(a.x + b.x, a.y + b.y, a.z + b.z, a.w + b.w);

    float s  = x.x + x.y + x.z + x.w;
    float sq = x.x * x.x + x.y * x.y + x.z * x.z + x.w * x.w;
#pragma unroll
    for (int off = 16; off; off >>= 1) {
        s  += __shfl_xor_sync(0xffffffffu, s,  off);
        sq += __shfl_xor_sync(0xffffffffu, sq, off);
    }
    __shared__ float ss[4], ssq[4];
    if ((tid & 31) == 0) { ss[tid >> 5] = s; ssq[tid >> 5] = sq; }
    __syncthreads();
    s  = ss[0] + ss[1] + ss[2] + ss[3];
    sq = ssq[0] + ssq[1] + ssq[2] + ssq[3];

    float mu  = s * (1.0f / D_);
    float var = sq * (1.0f / D_) - mu * mu;
    float inv = rsqrtf(var + 1e-5f);

    float4 gg = *(const float4*)&g[tid * 4];
    float4 bb = *(const float4*)&be[tid * 4];
    float4 oo = make_float4((x.x - mu) * inv * gg.x + bb.x,
                            (x.y - mu) * inv * gg.y + bb.y,
                            (x.z - mu) * inv * gg.z + bb.z,
                            (x.w - mu) * inv * gg.w + bb.w);
    *(float4*)&out[base + tid * 4] = oo;
    if (SPLIT) {
        uint32_t h0, l0, h1, l1;
        split2(oo.x, oo.y, h0, l0);
        split2(oo.z, oo.w, h1, l1);
        uint32_t* hp = (uint32_t*)&ohi[base + tid * 4];
        uint32_t* lp = (uint32_t*)&olo[base + tid * 4];
        hp[0] = h0; hp[1] = h1;
        lp[0] = l0; lp[1] = l1;
    }
}

// ---------------------------------------------------------------------------
// Launch
// ---------------------------------------------------------------------------
extern "C" void kernel_launch(void* const* d_in, const int* in_sizes, int n_in,
                              void* d_out, int out_size)
{
    const float* X    = (const float*)d_in[0];
    const float* ENC  = (const float*)d_in[1];
    const int*   DVL  = (const int*)d_in[2];
    const int*   EVL  = (const int*)d_in[3];
    const float* Wmat[8] = {
        (const float*)d_in[4],  (const float*)d_in[5],
        (const float*)d_in[6],  (const float*)d_in[7],
        (const float*)d_in[8],  (const float*)d_in[9],
        (const float*)d_in[10], (const float*)d_in[11]};
    const float* W1   = (const float*)d_in[12];
    const float* b1   = (const float*)d_in[13];
    const float* W2   = (const float*)d_in[14];
    const float* b2   = (const float*)d_in[15];
    const float* G1   = (const float*)d_in[16];
    const float* BE1  = (const float*)d_in[17];
    const float* G2   = (const float*)d_in[18];
    const float* BE2  = (const float*)d_in[19];
    const float* G3   = (const float*)d_in[20];
    const float* BE3  = (const float*)d_in[21];
    float* out = (float*)d_out;

    float *tmp, *Y, *Z;
    __nv_bfloat16 *h1, *l1, *h2, *l2, *qkvh, *qkvl, *kvh, *kvl;
    __nv_bfloat16 *q2h, *q2l, *ath, *atl, *Fh, *Fl, *Wh, *Wl;
    cudaGetSymbolAddress((void**)&tmp,  g_tmp);
    cudaGetSymbolAddress((void**)&Y,    g_Y);
    cudaGetSymbolAddress((void**)&Z,    g_Z);
    cudaGetSymbolAddress((void**)&h1,   g_h1);
    cudaGetSymbolAddress((void**)&l1,   g_l1);
    cudaGetSymbolAddress((void**)&h2,   g_h2);
    cudaGetSymbolAddress((void**)&l2,   g_l2);
    cudaGetSymbolAddress((void**)&qkvh, g_qkvh);
    cudaGetSymbolAddress((void**)&qkvl, g_qkvl);
    cudaGetSymbolAddress((void**)&kvh,  g_kvh);
    cudaGetSymbolAddress((void**)&kvl,  g_kvl);
    cudaGetSymbolAddress((void**)&q2h,  g_q2h);
    cudaGetSymbolAddress((void**)&q2l,  g_q2l);
    cudaGetSymbolAddress((void**)&ath,  g_ath);
    cudaGetSymbolAddress((void**)&atl,  g_atl);
    cudaGetSymbolAddress((void**)&Fh,   g_Fh);
    cudaGetSymbolAddress((void**)&Fl,   g_Fl);
    cudaGetSymbolAddress((void**)&Wh,   g_Wh);
    cudaGetSymbolAddress((void**)&Wl,   g_Wl);

    cudaFuncSetAttribute(attn_hmma,
                         cudaFuncAttributeMaxDynamicSharedMemorySize, ATT_SMEM);
    cudaFuncSetAttribute(gemm_hmma<0, 0, 1>,
                         cudaFuncAttributeMaxDynamicSharedMemorySize, GEMM_SMEM);
    cudaFuncSetAttribute(gemm_hmma<0, 0, 0>,
                         cudaFuncAttributeMaxDynamicSharedMemorySize, GEMM_SMEM);
    cudaFuncSetAttribute(gemm_hmma<1, 1, 1>,
                         cudaFuncAttributeMaxDynamicSharedMemorySize, GEMM_SMEM);
    cudaFuncSetAttribute(gemm_hmma<1, 0, 0>,
                         cudaFuncAttributeMaxDynamicSharedMemorySize, GEMM_SMEM);

    size_t WO[10];
    for (int i = 0; i < 8; i++) WO[i] = (size_t)i * D_ * D_;
    WO[8] = 8ull * D_ * D_;
    WO[9] = WO[8] + (size_t)F_ * D_;

    const int nDD = D_ * D_ / 4;       // 65536
    const int nMD = M_ * D_ / 4;       // 2097152
    const int nFD = F_ * D_ / 4;       // 262144

    // one merged split launch: 8 DxD weights + W1 + W2 + X + ENC
    SplitSegs segs;
    int total4 = 0;
    for (int i = 0; i < 8; i++) {
        segs.src[i] = Wmat[i];
        segs.hi[i] = Wh + WO[i]; segs.lo[i] = Wl + WO[i];
        segs.n4[i] = nDD; total4 += nDD;
    }
    segs.src[8] = W1; segs.hi[8] = Wh + WO[8]; segs.lo[8] = Wl + WO[8];
    segs.n4[8] = nFD; total4 += nFD;
    segs.src[9] = W2; segs.hi[9] = Wh + WO[9]; segs.lo[9] = Wl + WO[9];
    segs.n4[9] = nFD; total4 += nFD;
    segs.src[10] = X;   segs.hi[10] = h1; segs.lo[10] = l1;
    segs.n4[10] = nMD; total4 += nMD;
    segs.src[11] = ENC; segs.hi[11] = h2; segs.lo[11] = l2;
    segs.n4[11] = nMD; total4 += nMD;
    msplit_kernel<<<(total4 + 255) / 256, 256>>>(segs);

    dim3 gQKV(1536 / 128, M_ / 128);   // (12, 128)
    dim3 gKV (1024 / 128, M_ / 128);   // (8, 128)
    dim3 gP  (D_ / 128,   M_ / 128);   // (4, 128)
    dim3 gF1 (F_ / 128,   M_ / 128);   // (16, 128)
    dim3 gA  (B_ * H_,    T_ / 128);   // (256, 4)

    // ---- self-attention ----
    gemm_hmma<0,0,1><<<gQKV, 256, GEMM_SMEM>>>(h1, l1, Wh + WO[0], Wl + WO[0],
                                               nullptr, nullptr, qkvh, qkvl, 1536, D_);
    attn_hmma<<<gA, 256, ATT_SMEM>>>(qkvh, qkvl, 1536,
                                     qkvh + 512, qkvl + 512,
                                     qkvh + 1024, qkvl + 1024, 1536,
                                     DVL, 1, ath, atl);
    gemm_hmma<0,0,0><<<gP, 256, GEMM_SMEM>>>(ath, atl, Wh + WO[3], Wl + WO[3],
                                             nullptr, tmp, nullptr, nullptr, D_, D_);
    addnorm_kernel<1><<<M_, 128>>>(X, tmp, G1, BE1, Y, h1, l1);

    // ---- cross-attention ----
    gemm_hmma<0,0,1><<<gP,  256, GEMM_SMEM>>>(h1, l1, Wh + WO[4], Wl + WO[4],
                                              nullptr, nullptr, q2h, q2l, D_, D_);
    gemm_hmma<0,0,1><<<gKV, 256, GEMM_SMEM>>>(h2, l2, Wh + WO[5], Wl + WO[5],
                                              nullptr, nullptr, kvh, kvl, 1024, D_);
    attn_hmma<<<gA, 256, ATT_SMEM>>>(q2h, q2l, D_,
                                     kvh, kvl,
                                     kvh + 512, kvl + 512, 1024,
                                     EVL, 0, ath, atl);
    gemm_hmma<0,0,0><<<gP, 256, GEMM_SMEM>>>(ath, atl, Wh + WO[7], Wl + WO[7],
                                             nullptr, tmp, nullptr, nullptr, D_, D_);
    addnorm_kernel<1><<<M_, 128>>>(Y, tmp, G2, BE2, Z, h2, l2);

    // ---- FFN ----
    gemm_hmma<1,1,1><<<gF1, 256, GEMM_SMEM>>>(h2, l2, Wh + WO[8], Wl + WO[8],
                                              b1, nullptr, Fh, Fl, F_, D_);
    gemm_hmma<1,0,0><<<gP, 256, GEMM_SMEM>>>(Fh, Fl, Wh + WO[9], Wl + WO[9],
                                             b2, tmp, nullptr, nullptr, D_, F_);
    addnorm_kernel<0><<<M_, 128>>>(Z, tmp, G3, BE3, out, nullptr, nullptr);
}

// round 7
// speedup vs baseline: 3.2251x; 1.1410x over previous
#include <cuda_runtime.h>
#include <cuda_bf16.h>
#include <math.h>
#include <stdint.h>

// Problem constants
#define B_ 32
#define T_ 512
#define D_ 512
#define H_ 8
#define M_ (B_ * T_)   // 16384 rows
#define F_ 2048

// ---------------------------------------------------------------------------
// Scratch (device globals; no allocation allowed)
// ---------------------------------------------------------------------------
__device__ float g_tmp[(size_t)M_ * D_];
__device__ float g_Y  [(size_t)M_ * D_];
__device__ float g_Z  [(size_t)M_ * D_];

__device__ __nv_bfloat16 g_h1  [(size_t)M_ * D_];     // X / Y split
__device__ __nv_bfloat16 g_l1  [(size_t)M_ * D_];
__device__ __nv_bfloat16 g_h2  [(size_t)M_ * D_];     // ENC / Z split
__device__ __nv_bfloat16 g_l2  [(size_t)M_ * D_];
__device__ __nv_bfloat16 g_qkvh[(size_t)M_ * 1536];   // self QKV fused
__device__ __nv_bfloat16 g_qkvl[(size_t)M_ * 1536];
__device__ __nv_bfloat16 g_kvh [(size_t)M_ * 1024];   // cross KV fused
__device__ __nv_bfloat16 g_kvl [(size_t)M_ * 1024];
__device__ __nv_bfloat16 g_q2h [(size_t)M_ * D_];     // cross Q
__device__ __nv_bfloat16 g_q2l [(size_t)M_ * D_];
__device__ __nv_bfloat16 g_ath [(size_t)M_ * D_];
__device__ __nv_bfloat16 g_atl [(size_t)M_ * D_];
__device__ __nv_bfloat16 g_Fh  [(size_t)M_ * F_];
__device__ __nv_bfloat16 g_Fl  [(size_t)M_ * F_];
__device__ __nv_bfloat16 g_Wh  [4194304];
__device__ __nv_bfloat16 g_Wl  [4194304];

// ---------------------------------------------------------------------------
// helpers
// ---------------------------------------------------------------------------
__device__ __forceinline__ uint32_t smem_u32(const void* p) {
    uint32_t a;
    asm("{ .reg .u64 t; cvta.to.shared.u64 t, %1; cvt.u32.u64 %0, t; }"
        : "=r"(a) : "l"(p));
    return a;
}

#define CP_ASYNC16(dst, src) \
    asm volatile("cp.async.cg.shared.global [%0], [%1], 16;" :: \
                 "r"(dst), "l"(src) : "memory")
#define CP_COMMIT() asm volatile("cp.async.commit_group;" ::: "memory")
#define CP_WAIT(n)  asm volatile("cp.async.wait_group %0;" :: "n"(n) : "memory")

#define LDMATRIX_X4(r0, r1, r2, r3, addr) \
    asm volatile("ldmatrix.sync.aligned.m8n8.x4.shared.b16 {%0,%1,%2,%3}, [%4];" \
                 : "=r"(r0), "=r"(r1), "=r"(r2), "=r"(r3) : "r"(addr))

#define LDMATRIX_X4_T(r0, r1, r2, r3, addr) \
    asm volatile("ldmatrix.sync.aligned.m8n8.x4.trans.shared.b16 {%0,%1,%2,%3}, [%4];" \
                 : "=r"(r0), "=r"(r1), "=r"(r2), "=r"(r3) : "r"(addr))

#define MMA_BF16(d0, d1, d2, d3, a0, a1, a2, a3, b0, b1) \
    asm volatile("mma.sync.aligned.m16n8k16.row.col.f32.bf16.bf16.f32 " \
                 "{%0,%1,%2,%3}, {%4,%5,%6,%7}, {%8,%9}, {%0,%1,%2,%3};" \
                 : "+f"(d0), "+f"(d1), "+f"(d2), "+f"(d3) \
                 : "r"(a0), "r"(a1), "r"(a2), "r"(a3), "r"(b0), "r"(b1))

__device__ __forceinline__ void split2(float x, float y, uint32_t& hi, uint32_t& lo) {
    __nv_bfloat162 h = __floats2bfloat162_rn(x, y);
    float hx = __low2float(h), hy = __high2float(h);
    __nv_bfloat162 l = __floats2bfloat162_rn(x - hx, y - hy);
    hi = *reinterpret_cast<uint32_t*>(&h);
    lo = *reinterpret_cast<uint32_t*>(&l);
}

// ---------------------------------------------------------------------------
// merged split: 12 segments in one launch
// ---------------------------------------------------------------------------
struct SplitSegs {
    const float* src[12];
    __nv_bfloat16* hi[12];
    __nv_bfloat16* lo[12];
    int n4[12];
};

__global__ void __launch_bounds__(256)
msplit_kernel(SplitSegs s)
{
    int i = blockIdx.x * 256 + threadIdx.x;
#pragma unroll
    for (int k = 0; k < 12; k++) {
        if (i < s.n4[k]) {
            float4 v = ((const float4*)s.src[k])[i];
            uint32_t h0, l0, h1, l1;
            split2(v.x, v.y, h0, l0);
            split2(v.z, v.w, h1, l1);
            uint32_t* hp = (uint32_t*)s.hi[k];
            uint32_t* lp = (uint32_t*)s.lo[k];
            hp[2 * i] = h0; hp[2 * i + 1] = h1;
            lp[2 * i] = l0; lp[2 * i + 1] = l1;
            return;
        }
        i -= s.n4[k];
    }
}

// ---------------------------------------------------------------------------
// HMMA GEMM body: C[M,N] = (Ah+Al)[M,K] @ (Bh+Bl)[N,K]^T (3-pass bf16 split)
// XOR-swizzled SMEM (64B rows), 3-stage cp.async pipeline, 1 barrier/chunk.
// swizzle: 16B-chunk c of row r lives at r*64 + ((c ^ ((r>>1)&3))<<4)
// ---------------------------------------------------------------------------
#define TILE_B 8192                  // 128 rows x 64 B
#define STAGE_B (4 * TILE_B)         // Ah, Al, Bh, Bl = 32768
#define GEMM_SMEM (3 * STAGE_B)      // 98304

template <int BIAS, int LEAKY, int SPLIT>
__device__ __forceinline__ void gemm_body(
    const __nv_bfloat16* __restrict__ Ah, const __nv_bfloat16* __restrict__ Al,
    const __nv_bfloat16* __restrict__ Bh, const __nv_bfloat16* __restrict__ Bl,
    const float* __restrict__ bias, float* __restrict__ C,
    __nv_bfloat16* __restrict__ Chi, __nv_bfloat16* __restrict__ Clo,
    int N, int K, int bm, int bn, char* smem)
{
    const uint32_t sbase = smem_u32(smem);

    const int tid = threadIdx.x;
    const int wid = tid >> 5, lane = tid & 31;
    const int wm = wid & 1, wn = wid >> 1;

    const int ldr0 = tid >> 2;            // row 0..63
    const int ldc4 = tid & 3;             // 16B-chunk 0..3
    const int ldce = ldc4 * 8;            // element col

    const __nv_bfloat16* gAh = Ah + (size_t)(bm + ldr0) * K + ldce;
    const __nv_bfloat16* gAl = Al + (size_t)(bm + ldr0) * K + ldce;
    const __nv_bfloat16* gBh = Bh + (size_t)(bn + ldr0) * K + ldce;
    const __nv_bfloat16* gBl = Bl + (size_t)(bn + ldr0) * K + ldce;
    const size_t rstep = (size_t)64 * K;

    // swizzled store offsets for the two row-halves (row-invariant per thread)
    uint32_t sro[2];
#pragma unroll
    for (int h = 0; h < 2; h++) {
        const int r = ldr0 + h * 64;
        sro[h] = (uint32_t)(r * 64 + ((ldc4 ^ ((r >> 1) & 3)) << 4));
    }

    // ldmatrix lane geometry (swizzle bits constant across frag index)
    const int aRowB = wm * 64 + (lane & 15);          // base row for A frags
    const int aKc0  = (lane >> 4);                    // chunk parity
    const int aSw   = (aRowB >> 1) & 3;
    const int bRowB = wn * 32 + (lane & 7) + ((lane >> 4) << 3);
    const int bKc0  = (lane >> 3) & 1;
    const int bSw   = (bRowB >> 1) & 3;

    float acc[4][4][4];
#pragma unroll
    for (int i = 0; i < 4; i++)
#pragma unroll
        for (int j = 0; j < 4; j++)
#pragma unroll
            for (int r = 0; r < 4; r++) acc[i][j][r] = 0.f;

    const int NC = K >> 5;

    auto load_chunk = [&](int c, int buf) {
        const uint32_t st = sbase + buf * STAGE_B;
        const int koff = c << 5;
#pragma unroll
        for (int h = 0; h < 2; h++) {
            CP_ASYNC16(st + sro[h],              gAh + (size_t)h * rstep + koff);
            CP_ASYNC16(st + TILE_B + sro[h],     gAl + (size_t)h * rstep + koff);
            CP_ASYNC16(st + 2 * TILE_B + sro[h], gBh + (size_t)h * rstep + koff);
            CP_ASYNC16(st + 3 * TILE_B + sro[h], gBl + (size_t)h * rstep + koff);
        }
        CP_COMMIT();
    };

    load_chunk(0, 0);
    load_chunk(1, 1);
    int lbuf = 2, cbuf = 0;

    for (int c = 0; c < NC; c++) {
        if (c + 1 < NC) { CP_WAIT(1); } else { CP_WAIT(0); }
        __syncthreads();
        if (c + 2 < NC) {
            load_chunk(c + 2, lbuf);
            lbuf = (lbuf == 2) ? 0 : lbuf + 1;
        }

        const uint32_t st  = sbase + cbuf * STAGE_B;
        cbuf = (cbuf == 2) ? 0 : cbuf + 1;
        const uint32_t aBh = st,              aBl = st + TILE_B;
        const uint32_t bBh = st + 2 * TILE_B, bBl = st + 3 * TILE_B;

#pragma unroll
        for (int ks = 0; ks < 2; ks++) {
            const uint32_t aoff = (uint32_t)(aRowB * 64 +
                                  (((ks * 2 + aKc0) ^ aSw) << 4));
            const uint32_t boff = (uint32_t)(bRowB * 64 +
                                  (((ks * 2 + bKc0) ^ bSw) << 4));

            // B frags hi + lo
            uint32_t bh[4][2], bl[4][2];
#pragma unroll
            for (int j2 = 0; j2 < 2; j2++) {
                uint32_t r0, r1, r2, r3;
                LDMATRIX_X4(r0, r1, r2, r3, bBh + boff + j2 * 1024);
                bh[j2 * 2 + 0][0] = r0; bh[j2 * 2 + 0][1] = r1;
                bh[j2 * 2 + 1][0] = r2; bh[j2 * 2 + 1][1] = r3;
                LDMATRIX_X4(r0, r1, r2, r3, bBl + boff + j2 * 1024);
                bl[j2 * 2 + 0][0] = r0; bl[j2 * 2 + 0][1] = r1;
                bl[j2 * 2 + 1][0] = r2; bl[j2 * 2 + 1][1] = r3;
            }
            // A hi frags: pass0 (Ah*Bh) + pass1 (Ah*Bl)
            uint32_t a[4][4];
#pragma unroll
            for (int i = 0; i < 4; i++)
                LDMATRIX_X4(a[i][0], a[i][1], a[i][2], a[i][3],
                            aBh + aoff + i * 1024);
#pragma unroll
            for (int i = 0; i < 4; i++)
#pragma unroll
                for (int j = 0; j < 4; j++)
                    MMA_BF16(acc[i][j][0], acc[i][j][1], acc[i][j][2], acc[i][j][3],
                             a[i][0], a[i][1], a[i][2], a[i][3], bh[j][0], bh[j][1]);
#pragma unroll
            for (int i = 0; i < 4; i++)
#pragma unroll
                for (int j = 0; j < 4; j++)
                    MMA_BF16(acc[i][j][0], acc[i][j][1], acc[i][j][2], acc[i][j][3],
                             a[i][0], a[i][1], a[i][2], a[i][3], bl[j][0], bl[j][1]);
            // A lo frags (reuse regs): pass2 (Al*Bh)
#pragma unroll
            for (int i = 0; i < 4; i++)
                LDMATRIX_X4(a[i][0], a[i][1], a[i][2], a[i][3],
                            aBl + aoff + i * 1024);
#pragma unroll
            for (int i = 0; i < 4; i++)
#pragma unroll
                for (int j = 0; j < 4; j++)
                    MMA_BF16(acc[i][j][0], acc[i][j][1], acc[i][j][2], acc[i][j][3],
                             a[i][0], a[i][1], a[i][2], a[i][3], bh[j][0], bh[j][1]);
        }
    }

    const int tg = lane >> 2;
    const int tc = (lane & 3) * 2;
#pragma unroll
    for (int i = 0; i < 4; i++) {
        const int r0 = bm + wm * 64 + i * 16 + tg;
#pragma unroll
        for (int j = 0; j < 4; j++) {
            const int col = bn + wn * 32 + j * 8 + tc;
            float v0 = acc[i][j][0], v1 = acc[i][j][1];
            float v2 = acc[i][j][2], v3 = acc[i][j][3];
            if (BIAS) {
                const float b0 = bias[col], b1 = bias[col + 1];
                v0 += b0; v1 += b1; v2 += b0; v3 += b1;
            }
            if (LEAKY) {
                v0 = v0 > 0.f ? v0 : 0.01f * v0;
                v1 = v1 > 0.f ? v1 : 0.01f * v1;
                v2 = v2 > 0.f ? v2 : 0.01f * v2;
                v3 = v3 > 0.f ? v3 : 0.01f * v3;
            }
            if (SPLIT) {
                uint32_t h01, l01, h23, l23;
                split2(v0, v1, h01, l01);
                split2(v2, v3, h23, l23);
                *(uint32_t*)&Chi[(size_t)r0 * N + col]       = h01;
                *(uint32_t*)&Clo[(size_t)r0 * N + col]       = l01;
                *(uint32_t*)&Chi[(size_t)(r0 + 8) * N + col] = h23;
                *(uint32_t*)&Clo[(size_t)(r0 + 8) * N + col] = l23;
            } else {
                *(float2*)&C[(size_t)r0 * N + col]       = make_float2(v0, v1);
                *(float2*)&C[(size_t)(r0 + 8) * N + col] = make_float2(v2, v3);
            }
        }
    }
}

template <int BIAS, int LEAKY, int SPLIT>
__global__ void __launch_bounds__(256, 2)
gemm_hmma(const __nv_bfloat16* __restrict__ Ah, const __nv_bfloat16* __restrict__ Al,
          const __nv_bfloat16* __restrict__ Bh, const __nv_bfloat16* __restrict__ Bl,
          const float* __restrict__ bias, float* __restrict__ C,
          __nv_bfloat16* __restrict__ Chi, __nv_bfloat16* __restrict__ Clo,
          int N, int K)
{
    extern __shared__ __align__(16) char smem[];
    gemm_body<BIAS, LEAKY, SPLIT>(Ah, Al, Bh, Bl, bias, C, Chi, Clo,
                                  N, K, blockIdx.y * 128, blockIdx.x * 128, smem);
}

// Two independent SPLIT GEMM jobs in one launch (cross-attn Q2 + KV)
__global__ void __launch_bounds__(256, 2)
gemm_dual(const __nv_bfloat16* A0h, const __nv_bfloat16* A0l,
          const __nv_bfloat16* W0h, const __nv_bfloat16* W0l,
          __nv_bfloat16* C0h, __nv_bfloat16* C0l, int N0, int nb0,
          const __nv_bfloat16* A1h, const __nv_bfloat16* A1l,
          const __nv_bfloat16* W1h, const __nv_bfloat16* W1l,
          __nv_bfloat16* C1h, __nv_bfloat16* C1l, int N1, int K)
{
    extern __shared__ __align__(16) char smem[];
    if ((int)blockIdx.x < nb0)
        gemm_body<0, 0, 1>(A0h, A0l, W0h, W0l, nullptr, nullptr, C0h, C0l,
                           N0, K, blockIdx.y * 128, blockIdx.x * 128, smem);
    else
        gemm_body<0, 0, 1>(A1h, A1l, W1h, W1l, nullptr, nullptr, C1h, C1l,
                           N1, K, blockIdx.y * 128, (blockIdx.x - nb0) * 128, smem);
}

// ---------------------------------------------------------------------------
// HMMA flash attention, split-bf16 (unchanged from R6)
// ---------------------------------------------------------------------------
#define AROWB 144
#define ATT_SMEM (128 * AROWB * 2 + 64 * AROWB * 4)   // 73728

__global__ void __launch_bounds__(256, 2)
attn_hmma(const __nv_bfloat16* __restrict__ Qh, const __nv_bfloat16* __restrict__ Ql,
          int qs,
          const __nv_bfloat16* __restrict__ Kh, const __nv_bfloat16* __restrict__ Kl,
          const __nv_bfloat16* __restrict__ Vh, const __nv_bfloat16* __restrict__ Vl,
          int kvs,
          const int* __restrict__ vlp, int per_row,
          __nv_bfloat16* __restrict__ Oh, __nv_bfloat16* __restrict__ Ol)
{
    extern __shared__ __align__(16) char sm[];
    char* cQh = sm;
    char* cQl = sm + 18432;
    char* cKh = sm + 36864;
    char* cKl = sm + 46080;
    char* cVh = sm + 55296;
    char* cVl = sm + 64512;
    const uint32_t uQh = smem_u32(cQh), uQl = smem_u32(cQl);
    const uint32_t uKh = smem_u32(cKh), uKl = smem_u32(cKl);
    const uint32_t uVh = smem_u32(cVh), uVl = smem_u32(cVl);
    __shared__ int sred[8];

    const int tid = threadIdx.x;
    const int w = tid >> 5, lane = tid & 31;
    const int g = lane >> 2, c = lane & 3;
    const int b = blockIdx.x >> 3, h = blockIdx.x & 7;
    const int q0 = blockIdx.y * 128;

    int kmax;
    if (per_row) {
        int v = (tid < 128) ? vlp[b * T_ + q0 + tid] : 0;
#pragma unroll
        for (int off = 16; off; off >>= 1)
            v = max(v, __shfl_xor_sync(0xffffffffu, v, off));
        if (lane == 0) sred[w] = v;
        __syncthreads();
        kmax = sred[0];
#pragma unroll
        for (int i = 1; i < 8; i++) kmax = max(kmax, sred[i]);
    } else {
        kmax = vlp[b];
    }
    const int nkt = (kmax + 63) >> 6;

    const __nv_bfloat16* qhp = Qh + (size_t)(b * T_ + q0) * qs + h * 64;
    const __nv_bfloat16* qlp = Ql + (size_t)(b * T_ + q0) * qs + h * 64;
    for (int i = tid; i < 1024; i += 256) {
        const int r = i >> 3, ch = i & 7;
        const size_t go = (size_t)r * qs + ch * 8;
        const uint32_t so = r * AROWB + ch * 16;
        *(uint4*)(cQh + so) = *(const uint4*)(qhp + go);
        *(uint4*)(cQl + so) = *(const uint4*)(qlp + go);
    }
    __syncthreads();

    int vl0, vl1;
    if (per_row) {
        vl0 = vlp[b * T_ + q0 + w * 16 + g];
        vl1 = vlp[b * T_ + q0 + w * 16 + g + 8];
    } else {
        vl0 = vl1 = kmax;
    }

    float m0 = -1e30f, m1 = -1e30f, l0 = 0.f, l1 = 0.f;
    float o[8][4];
#pragma unroll
    for (int j = 0; j < 8; j++)
#pragma unroll
        for (int e = 0; e < 4; e++) o[j][e] = 0.f;

    const uint32_t qaddr = (w * 16 + (lane & 15)) * AROWB + (lane >> 4) * 16;
    const int bRow = (lane & 7) + ((lane >> 4) << 3);
    const int bK8  = ((lane >> 3) & 1) * 16;
    const int vRow = (lane & 7) + ((lane >> 3) & 1) * 8;
    const int vColB = (lane >> 4) * 16;

    for (int kt = 0; kt < nkt; kt++) {
        __syncthreads();
        const size_t kb = (size_t)(b * T_ + kt * 64) * kvs + h * 64;
        for (int i = tid; i < 512; i += 256) {
            const int r = i >> 3, ch = i & 7;
            const size_t go = kb + (size_t)r * kvs + ch * 8;
            const uint32_t so = r * AROWB + ch * 16;
            *(uint4*)(cKh + so) = *(const uint4*)(Kh + go);
            *(uint4*)(cKl + so) = *(const uint4*)(Kl + go);
            *(uint4*)(cVh + so) = *(const uint4*)(Vh + go);
            *(uint4*)(cVl + so) = *(const uint4*)(Vl + go);
        }
        __syncthreads();

        float s[8][4];
#pragma unroll
        for (int j = 0; j < 8; j++)
#pragma unroll
            for (int e = 0; e < 4; e++) s[j][e] = 0.f;

#pragma unroll
        for (int kk = 0; kk < 4; kk++) {
            uint32_t ah0, ah1, ah2, ah3, al0, al1, al2, al3;
            LDMATRIX_X4(ah0, ah1, ah2, ah3, uQh + qaddr + kk * 32);
            LDMATRIX_X4(al0, al1, al2, al3, uQl + qaddr + kk * 32);
#pragma unroll
            for (int j2 = 0; j2 < 4; j2++) {
                uint32_t r0, r1, r2, r3;
                LDMATRIX_X4(r0, r1, r2, r3,
                            uKh + (j2 * 16 + bRow) * AROWB + kk * 32 + bK8);
                MMA_BF16(s[2*j2][0], s[2*j2][1], s[2*j2][2], s[2*j2][3],
                         ah0, ah1, ah2, ah3, r0, r1);
                MMA_BF16(s[2*j2+1][0], s[2*j2+1][1], s[2*j2+1][2], s[2*j2+1][3],
                         ah0, ah1, ah2, ah3, r2, r3);
                MMA_BF16(s[2*j2][0], s[2*j2][1], s[2*j2][2], s[2*j2][3],
                         al0, al1, al2, al3, r0, r1);
                MMA_BF16(s[2*j2+1][0], s[2*j2+1][1], s[2*j2+1][2], s[2*j2+1][3],
                         al0, al1, al2, al3, r2, r3);
            }
#pragma unroll
            for (int j2 = 0; j2 < 4; j2++) {
                uint32_t r0, r1, r2, r3;
                LDMATRIX_X4(r0, r1, r2, r3,
                            uKl + (j2 * 16 + bRow) * AROWB + kk * 32 + bK8);
                MMA_BF16(s[2*j2][0], s[2*j2][1], s[2*j2][2], s[2*j2][3],
                         ah0, ah1, ah2, ah3, r0, r1);
                MMA_BF16(s[2*j2+1][0], s[2*j2+1][1], s[2*j2+1][2], s[2*j2+1][3],
                         ah0, ah1, ah2, ah3, r2, r3);
            }
        }

        const int kof = kt * 64 + c * 2;
        float mx0 = -1e30f, mx1 = -1e30f;
#pragma unroll
        for (int j = 0; j < 8; j++) {
            const int ki = kof + j * 8;
            s[j][0] = (ki     < vl0) ? s[j][0] * 0.125f : -1e10f;
            s[j][1] = (ki + 1 < vl0) ? s[j][1] * 0.125f : -1e10f;
            s[j][2] = (ki     < vl1) ? s[j][2] * 0.125f : -1e10f;
            s[j][3] = (ki + 1 < vl1) ? s[j][3] * 0.125f : -1e10f;
            mx0 = fmaxf(mx0, fmaxf(s[j][0], s[j][1]));
            mx1 = fmaxf(mx1, fmaxf(s[j][2], s[j][3]));
        }
        mx0 = fmaxf(mx0, __shfl_xor_sync(0xffffffffu, mx0, 1));
        mx0 = fmaxf(mx0, __shfl_xor_sync(0xffffffffu, mx0, 2));
        mx1 = fmaxf(mx1, __shfl_xor_sync(0xffffffffu, mx1, 1));
        mx1 = fmaxf(mx1, __shfl_xor_sync(0xffffffffu, mx1, 2));

        const float mn0 = fmaxf(m0, mx0), mn1 = fmaxf(m1, mx1);
        const float al_0 = __expf(m0 - mn0), al_1 = __expf(m1 - mn1);
        m0 = mn0; m1 = mn1;

        float rs0 = 0.f, rs1 = 0.f;
#pragma unroll
        for (int j = 0; j < 8; j++) {
            s[j][0] = __expf(s[j][0] - mn0);
            s[j][1] = __expf(s[j][1] - mn0);
            s[j][2] = __expf(s[j][2] - mn1);
            s[j][3] = __expf(s[j][3] - mn1);
            rs0 += s[j][0] + s[j][1];
            rs1 += s[j][2] + s[j][3];
        }
        rs0 += __shfl_xor_sync(0xffffffffu, rs0, 1);
        rs0 += __shfl_xor_sync(0xffffffffu, rs0, 2);
        rs1 += __shfl_xor_sync(0xffffffffu, rs1, 1);
        rs1 += __shfl_xor_sync(0xffffffffu, rs1, 2);
        l0 = l0 * al_0 + rs0;
        l1 = l1 * al_1 + rs1;

#pragma unroll
        for (int j = 0; j < 8; j++) {
            o[j][0] *= al_0; o[j][1] *= al_0;
            o[j][2] *= al_1; o[j][3] *= al_1;
        }

#pragma unroll
        for (int t = 0; t < 4; t++) {
            uint32_t ph[4], pl[4];
            split2(s[2*t][0],   s[2*t][1],   ph[0], pl[0]);
            split2(s[2*t][2],   s[2*t][3],   ph[1], pl[1]);
            split2(s[2*t+1][0], s[2*t+1][1], ph[2], pl[2]);
            split2(s[2*t+1][2], s[2*t+1][3], ph[3], pl[3]);
#pragma unroll
            for (int j2 = 0; j2 < 4; j2++) {
                uint32_t r0, r1, r2, r3;
                LDMATRIX_X4_T(r0, r1, r2, r3,
                              uVh + (t * 16 + vRow) * AROWB + j2 * 32 + vColB);
                MMA_BF16(o[2*j2][0], o[2*j2][1], o[2*j2][2], o[2*j2][3],
                         ph[0], ph[1], ph[2], ph[3], r0, r1);
                MMA_BF16(o[2*j2+1][0], o[2*j2+1][1], o[2*j2+1][2], o[2*j2+1][3],
                         ph[0], ph[1], ph[2], ph[3], r2, r3);
                MMA_BF16(o[2*j2][0], o[2*j2][1], o[2*j2][2], o[2*j2][3],
                         pl[0], pl[1], pl[2], pl[3], r0, r1);
                MMA_BF16(o[2*j2+1][0], o[2*j2+1][1], o[2*j2+1][2], o[2*j2+1][3],
                         pl[0], pl[1], pl[2], pl[3], r2, r3);
            }
#pragma unroll
            for (int j2 = 0; j2 < 4; j2++) {
                uint32_t r0, r1, r2, r3;
                LDMATRIX_X4_T(r0, r1, r2, r3,
                              uVl + (t * 16 + vRow) * AROWB + j2 * 32 + vColB);
                MMA_BF16(o[2*j2][0], o[2*j2][1], o[2*j2][2], o[2*j2][3],
                         ph[0], ph[1], ph[2], ph[3], r0, r1);
                MMA_BF16(o[2*j2+1][0], o[2*j2+1][1], o[2*j2+1][2], o[2*j2+1][3],
                         ph[0], ph[1], ph[2], ph[3], r2, r3);
            }
        }
    }

    const float il0 = 1.0f / l0, il1 = 1.0f / l1;
    const int r0g = b * T_ + q0 + w * 16 + g;
    const int r1g = r0g + 8;
#pragma unroll
    for (int j = 0; j < 8; j++) {
        const int col = h * 64 + j * 8 + c * 2;
        uint32_t hi, lo;
        split2(o[j][0] * il0, o[j][1] * il0, hi, lo);
        *(uint32_t*)&Oh[(size_t)r0g * D_ + col] = hi;
        *(uint32_t*)&Ol[(size_t)r0g * D_ + col] = lo;
        split2(o[j][2] * il1, o[j][3] * il1, hi, lo);
        *(uint32_t*)&Oh[(size_t)r1g * D_ + col] = hi;
        *(uint32_t*)&Ol[(size_t)r1g * D_ + col] = lo;
    }
}

// ---------------------------------------------------------------------------
// out = LayerNorm(A + Bt) * g + be ; SPLIT=1 also emits bf16 hi/lo
// ---------------------------------------------------------------------------
template <int SPLIT>
__global__ void __launch_bounds__(128)
addnorm_kernel(const float* __restrict__ A, const float* __restrict__ Bt,
               const float* __restrict__ g, const float* __restrict__ be,
               float* __restrict__ out,
               __nv_bfloat16* __restrict__ ohi, __nv_bfloat16* __restrict__ olo)
{
    const int row = blockIdx.x;
    const int tid = threadIdx.x;
    const size_t base = (size_t)row * D_;

    float4 a = *(const float4*)&A[base + tid * 4];
    float4 b = *(const float4*)&Bt[base + tid * 4];
    float4 x = make_float4(a.x + b.x, a.y + b.y, a.z + b.z, a.w + b.w);

    float s  = x.x + x.y + x.z + x.w;
    float sq = x.x * x.x + x.y * x.y + x.z * x.z + x.w * x.w;
#pragma unroll
    for (int off = 16; off; off >>= 1) {
        s  += __shfl_xor_sync(0xffffffffu, s,  off);
        sq += __shfl_xor_sync(0xffffffffu, sq, off);
    }
    __shared__ float ss[4], ssq[4];
    if ((tid & 31) == 0) { ss[tid >> 5] = s; ssq[tid >> 5] = sq; }
    __syncthreads();
    s  = ss[0] + ss[1] + ss[2] + ss[3];
    sq = ssq[0] + ssq[1] + ssq[2] + ssq[3];

    float mu  = s * (1.0f / D_);
    float var = sq * (1.0f / D_) - mu * mu;
    float inv = rsqrtf(var + 1e-5f);

    float4 gg = *(const float4*)&g[tid * 4];
    float4 bb = *(const float4*)&be[tid * 4];
    float4 oo = make_float4((x.x - mu) * inv * gg.x + bb.x,
                            (x.y - mu) * inv * gg.y + bb.y,
                            (x.z - mu) * inv * gg.z + bb.z,
                            (x.w - mu) * inv * gg.w + bb.w);
    *(float4*)&out[base + tid * 4] = oo;
    if (SPLIT) {
        uint32_t h0, l0, h1, l1;
        split2(oo.x, oo.y, h0, l0);
        split2(oo.z, oo.w, h1, l1);
        uint32_t* hp = (uint32_t*)&ohi[base + tid * 4];
        uint32_t* lp = (uint32_t*)&olo[base + tid * 4];
        hp[0] = h0; hp[1] = h1;
        lp[0] = l0; lp[1] = l1;
    }
}

// ---------------------------------------------------------------------------
// Launch
// ---------------------------------------------------------------------------
extern "C" void kernel_launch(void* const* d_in, const int* in_sizes, int n_in,
                              void* d_out, int out_size)
{
    const float* X    = (const float*)d_in[0];
    const float* ENC  = (const float*)d_in[1];
    const int*   DVL  = (const int*)d_in[2];
    const int*   EVL  = (const int*)d_in[3];
    const float* Wmat[8] = {
        (const float*)d_in[4],  (const float*)d_in[5],
        (const float*)d_in[6],  (const float*)d_in[7],
        (const float*)d_in[8],  (const float*)d_in[9],
        (const float*)d_in[10], (const float*)d_in[11]};
    const float* W1   = (const float*)d_in[12];
    const float* b1   = (const float*)d_in[13];
    const float* W2   = (const float*)d_in[14];
    const float* b2   = (const float*)d_in[15];
    const float* G1   = (const float*)d_in[16];
    const float* BE1  = (const float*)d_in[17];
    const float* G2   = (const float*)d_in[18];
    const float* BE2  = (const float*)d_in[19];
    const float* G3   = (const float*)d_in[20];
    const float* BE3  = (const float*)d_in[21];
    float* out = (float*)d_out;

    float *tmp, *Y, *Z;
    __nv_bfloat16 *h1, *l1, *h2, *l2, *qkvh, *qkvl, *kvh, *kvl;
    __nv_bfloat16 *q2h, *q2l, *ath, *atl, *Fh, *Fl, *Wh, *Wl;
    cudaGetSymbolAddress((void**)&tmp,  g_tmp);
    cudaGetSymbolAddress((void**)&Y,    g_Y);
    cudaGetSymbolAddress((void**)&Z,    g_Z);
    cudaGetSymbolAddress((void**)&h1,   g_h1);
    cudaGetSymbolAddress((void**)&l1,   g_l1);
    cudaGetSymbolAddress((void**)&h2,   g_h2);
    cudaGetSymbolAddress((void**)&l2,   g_l2);
    cudaGetSymbolAddress((void**)&qkvh, g_qkvh);
    cudaGetSymbolAddress((void**)&qkvl, g_qkvl);
    cudaGetSymbolAddress((void**)&kvh,  g_kvh);
    cudaGetSymbolAddress((void**)&kvl,  g_kvl);
    cudaGetSymbolAddress((void**)&q2h,  g_q2h);
    cudaGetSymbolAddress((void**)&q2l,  g_q2l);
    cudaGetSymbolAddress((void**)&ath,  g_ath);
    cudaGetSymbolAddress((void**)&atl,  g_atl);
    cudaGetSymbolAddress((void**)&Fh,   g_Fh);
    cudaGetSymbolAddress((void**)&Fl,   g_Fl);
    cudaGetSymbolAddress((void**)&Wh,   g_Wh);
    cudaGetSymbolAddress((void**)&Wl,   g_Wl);

    cudaFuncSetAttribute(attn_hmma,
                         cudaFuncAttributeMaxDynamicSharedMemorySize, ATT_SMEM);
    cudaFuncSetAttribute(gemm_hmma<0, 0, 1>,
                         cudaFuncAttributeMaxDynamicSharedMemorySize, GEMM_SMEM);
    cudaFuncSetAttribute(gemm_hmma<0, 0, 0>,
                         cudaFuncAttributeMaxDynamicSharedMemorySize, GEMM_SMEM);
    cudaFuncSetAttribute(gemm_hmma<1, 1, 1>,
                         cudaFuncAttributeMaxDynamicSharedMemorySize, GEMM_SMEM);
    cudaFuncSetAttribute(gemm_hmma<1, 0, 0>,
                         cudaFuncAttributeMaxDynamicSharedMemorySize, GEMM_SMEM);
    cudaFuncSetAttribute(gemm_dual,
                         cudaFuncAttributeMaxDynamicSharedMemorySize, GEMM_SMEM);

    size_t WO[10];
    for (int i = 0; i < 8; i++) WO[i] = (size_t)i * D_ * D_;
    WO[8] = 8ull * D_ * D_;
    WO[9] = WO[8] + (size_t)F_ * D_;

    const int nDD = D_ * D_ / 4;       // 65536
    const int nMD = M_ * D_ / 4;       // 2097152
    const int nFD = F_ * D_ / 4;       // 262144

    SplitSegs segs;
    int total4 = 0;
    for (int i = 0; i < 8; i++) {
        segs.src[i] = Wmat[i];
        segs.hi[i] = Wh + WO[i]; segs.lo[i] = Wl + WO[i];
        segs.n4[i] = nDD; total4 += nDD;
    }
    segs.src[8] = W1; segs.hi[8] = Wh + WO[8]; segs.lo[8] = Wl + WO[8];
    segs.n4[8] = nFD; total4 += nFD;
    segs.src[9] = W2; segs.hi[9] = Wh + WO[9]; segs.lo[9] = Wl + WO[9];
    segs.n4[9] = nFD; total4 += nFD;
    segs.src[10] = X;   segs.hi[10] = h1; segs.lo[10] = l1;
    segs.n4[10] = nMD; total4 += nMD;
    segs.src[11] = ENC; segs.hi[11] = h2; segs.lo[11] = l2;
    segs.n4[11] = nMD; total4 += nMD;
    msplit_kernel<<<(total4 + 255) / 256, 256>>>(segs);

    dim3 gQKV(1536 / 128, M_ / 128);   // (12, 128)
    dim3 gDUO(12,         M_ / 128);   // q2(4) + kv(8)
    dim3 gP  (D_ / 128,   M_ / 128);   // (4, 128)
    dim3 gF1 (F_ / 128,   M_ / 128);   // (16, 128)
    dim3 gA  (B_ * H_,    T_ / 128);   // (256, 4)

    // ---- self-attention ----
    gemm_hmma<0,0,1><<<gQKV, 256, GEMM_SMEM>>>(h1, l1, Wh + WO[0], Wl + WO[0],
                                               nullptr, nullptr, qkvh, qkvl, 1536, D_);
    attn_hmma<<<gA, 256, ATT_SMEM>>>(qkvh, qkvl, 1536,
                                     qkvh + 512, qkvl + 512,
                                     qkvh + 1024, qkvl + 1024, 1536,
                                     DVL, 1, ath, atl);
    gemm_hmma<0,0,0><<<gP, 256, GEMM_SMEM>>>(ath, atl, Wh + WO[3], Wl + WO[3],
                                             nullptr, tmp, nullptr, nullptr, D_, D_);
    addnorm_kernel<1><<<M_, 128>>>(X, tmp, G1, BE1, Y, h1, l1);

    // ---- cross-attention (Q2 + KV in one launch) ----
    gemm_dual<<<gDUO, 256, GEMM_SMEM>>>(h1, l1, Wh + WO[4], Wl + WO[4],
                                        q2h, q2l, 512, 4,
                                        h2, l2, Wh + WO[5], Wl + WO[5],
                                        kvh, kvl, 1024, D_);
    attn_hmma<<<gA, 256, ATT_SMEM>>>(q2h, q2l, D_,
                                     kvh, kvl,
                                     kvh + 512, kvl + 512, 1024,
                                     EVL, 0, ath, atl);
    gemm_hmma<0,0,0><<<gP, 256, GEMM_SMEM>>>(ath, atl, Wh + WO[7], Wl + WO[7],
                                             nullptr, tmp, nullptr, nullptr, D_, D_);
    addnorm_kernel<1><<<M_, 128>>>(Y, tmp, G2, BE2, Z, h2, l2);

    // ---- FFN ----
    gemm_hmma<1,1,1><<<gF1, 256, GEMM_SMEM>>>(h2, l2, Wh + WO[8], Wl + WO[8],
                                              b1, nullptr, Fh, Fl, F_, D_);
    gemm_hmma<1,0,0><<<gP, 256, GEMM_SMEM>>>(Fh, Fl, Wh + WO[9], Wl + WO[9],
                                             b2, tmp, nullptr, nullptr, D_, F_);
    addnorm_kernel<0><<<M_, 128>>>(Z, tmp, G3, BE3, out, nullptr, nullptr);
}

// round 8
// speedup vs baseline: 3.2595x; 1.0107x over previous
#include <cuda_runtime.h>
#include <cuda_bf16.h>
#include <math.h>
#include <stdint.h>

// Problem constants
#define B_ 32
#define T_ 512
#define D_ 512
#define H_ 8
#define M_ (B_ * T_)   // 16384 rows
#define F_ 2048

// ---------------------------------------------------------------------------
// Scratch (device globals; no allocation allowed)
// ---------------------------------------------------------------------------
__device__ float g_tmp[(size_t)M_ * D_];
__device__ float g_Y  [(size_t)M_ * D_];
__device__ float g_Z  [(size_t)M_ * D_];

__device__ __nv_bfloat16 g_h1  [(size_t)M_ * D_];     // X / Y split
__device__ __nv_bfloat16 g_l1  [(size_t)M_ * D_];
__device__ __nv_bfloat16 g_h2  [(size_t)M_ * D_];     // ENC / Z split
__device__ __nv_bfloat16 g_l2  [(size_t)M_ * D_];
__device__ __nv_bfloat16 g_qkvh[(size_t)M_ * 1536];   // self QKV fused
__device__ __nv_bfloat16 g_qkvl[(size_t)M_ * 1536];
__device__ __nv_bfloat16 g_kvh [(size_t)M_ * 1024];   // cross KV fused
__device__ __nv_bfloat16 g_kvl [(size_t)M_ * 1024];
__device__ __nv_bfloat16 g_q2h [(size_t)M_ * D_];     // cross Q
__device__ __nv_bfloat16 g_q2l [(size_t)M_ * D_];
__device__ __nv_bfloat16 g_ath [(size_t)M_ * D_];
__device__ __nv_bfloat16 g_atl [(size_t)M_ * D_];
__device__ __nv_bfloat16 g_Fh  [(size_t)M_ * F_];
__device__ __nv_bfloat16 g_Fl  [(size_t)M_ * F_];
__device__ __nv_bfloat16 g_Wh  [4194304];
__device__ __nv_bfloat16 g_Wl  [4194304];

// ---------------------------------------------------------------------------
// helpers
// ---------------------------------------------------------------------------
__device__ __forceinline__ uint32_t smem_u32(const void* p) {
    uint32_t a;
    asm("{ .reg .u64 t; cvta.to.shared.u64 t, %1; cvt.u32.u64 %0, t; }"
        : "=r"(a) : "l"(p));
    return a;
}

#define PDL_TRIGGER() asm volatile("griddepcontrol.launch_dependents;" ::: "memory")
#define PDL_WAIT()    asm volatile("griddepcontrol.wait;" ::: "memory")

#define CP_ASYNC16(dst, src) \
    asm volatile("cp.async.cg.shared.global [%0], [%1], 16;" :: \
                 "r"(dst), "l"(src) : "memory")
#define CP_COMMIT() asm volatile("cp.async.commit_group;" ::: "memory")
#define CP_WAIT(n)  asm volatile("cp.async.wait_group %0;" :: "n"(n) : "memory")

#define LDMATRIX_X4(r0, r1, r2, r3, addr) \
    asm volatile("ldmatrix.sync.aligned.m8n8.x4.shared.b16 {%0,%1,%2,%3}, [%4];" \
                 : "=r"(r0), "=r"(r1), "=r"(r2), "=r"(r3) : "r"(addr))

#define LDMATRIX_X4_T(r0, r1, r2, r3, addr) \
    asm volatile("ldmatrix.sync.aligned.m8n8.x4.trans.shared.b16 {%0,%1,%2,%3}, [%4];" \
                 : "=r"(r0), "=r"(r1), "=r"(r2), "=r"(r3) : "r"(addr))

#define MMA_BF16(d0, d1, d2, d3, a0, a1, a2, a3, b0, b1) \
    asm volatile("mma.sync.aligned.m16n8k16.row.col.f32.bf16.bf16.f32 " \
                 "{%0,%1,%2,%3}, {%4,%5,%6,%7}, {%8,%9}, {%0,%1,%2,%3};" \
                 : "+f"(d0), "+f"(d1), "+f"(d2), "+f"(d3) \
                 : "r"(a0), "r"(a1), "r"(a2), "r"(a3), "r"(b0), "r"(b1))

__device__ __forceinline__ void split2(float x, float y, uint32_t& hi, uint32_t& lo) {
    __nv_bfloat162 h = __floats2bfloat162_rn(x, y);
    float hx = __low2float(h), hy = __high2float(h);
    __nv_bfloat162 l = __floats2bfloat162_rn(x - hx, y - hy);
    hi = *reinterpret_cast<uint32_t*>(&h);
    lo = *reinterpret_cast<uint32_t*>(&l);
}

// ---------------------------------------------------------------------------
// merged split: 12 segments in one launch
// ---------------------------------------------------------------------------
struct SplitSegs {
    const float* src[12];
    __nv_bfloat16* hi[12];
    __nv_bfloat16* lo[12];
    int n4[12];
};

__global__ void __launch_bounds__(256)
msplit_kernel(SplitSegs s)
{
    PDL_TRIGGER();
    int i = blockIdx.x * 256 + threadIdx.x;
#pragma unroll
    for (int k = 0; k < 12; k++) {
        if (i < s.n4[k]) {
            float4 v = ((const float4*)s.src[k])[i];
            uint32_t h0, l0, h1, l1;
            split2(v.x, v.y, h0, l0);
            split2(v.z, v.w, h1, l1);
            uint32_t* hp = (uint32_t*)s.hi[k];
            uint32_t* lp = (uint32_t*)s.lo[k];
            hp[2 * i] = h0; hp[2 * i + 1] = h1;
            lp[2 * i] = l0; lp[2 * i + 1] = l1;
            return;
        }
        i -= s.n4[k];
    }
}

// ---------------------------------------------------------------------------
// HMMA GEMM body (3-pass bf16 split), XOR-swizzled SMEM, 3-stage cp.async
// ---------------------------------------------------------------------------
#define TILE_B 8192                  // 128 rows x 64 B
#define STAGE_B (4 * TILE_B)         // 32768
#define GEMM_SMEM (3 * STAGE_B)      // 98304

template <int BIAS, int LEAKY, int SPLIT>
__device__ __forceinline__ void gemm_body(
    const __nv_bfloat16* __restrict__ Ah, const __nv_bfloat16* __restrict__ Al,
    const __nv_bfloat16* __restrict__ Bh, const __nv_bfloat16* __restrict__ Bl,
    const float* __restrict__ bias, float* __restrict__ C,
    __nv_bfloat16* __restrict__ Chi, __nv_bfloat16* __restrict__ Clo,
    int N, int K, int bm, int bn, char* smem)
{
    PDL_TRIGGER();
    const uint32_t sbase = smem_u32(smem);

    const int tid = threadIdx.x;
    const int wid = tid >> 5, lane = tid & 31;
    const int wm = wid & 1, wn = wid >> 1;

    const int ldr0 = tid >> 2;            // row 0..63
    const int ldc4 = tid & 3;             // 16B-chunk 0..3
    const int ldce = ldc4 * 8;            // element col

    const __nv_bfloat16* gAh = Ah + (size_t)(bm + ldr0) * K + ldce;
    const __nv_bfloat16* gAl = Al + (size_t)(bm + ldr0) * K + ldce;
    const __nv_bfloat16* gBh = Bh + (size_t)(bn + ldr0) * K + ldce;
    const __nv_bfloat16* gBl = Bl + (size_t)(bn + ldr0) * K + ldce;
    const size_t rstep = (size_t)64 * K;

    uint32_t sro[2];
#pragma unroll
    for (int h = 0; h < 2; h++) {
        const int r = ldr0 + h * 64;
        sro[h] = (uint32_t)(r * 64 + ((ldc4 ^ ((r >> 1) & 3)) << 4));
    }

    const int aRowB = wm * 64 + (lane & 15);
    const int aKc0  = (lane >> 4);
    const int aSw   = (aRowB >> 1) & 3;
    const int bRowB = wn * 32 + (lane & 7) + ((lane >> 4) << 3);
    const int bKc0  = (lane >> 3) & 1;
    const int bSw   = (bRowB >> 1) & 3;

    float acc[4][4][4];
#pragma unroll
    for (int i = 0; i < 4; i++)
#pragma unroll
        for (int j = 0; j < 4; j++)
#pragma unroll
            for (int r = 0; r < 4; r++) acc[i][j][r] = 0.f;

    const int NC = K >> 5;

    auto load_chunk = [&](int c, int buf) {
        const uint32_t st = sbase + buf * STAGE_B;
        const int koff = c << 5;
#pragma unroll
        for (int h = 0; h < 2; h++) {
            CP_ASYNC16(st + sro[h],              gAh + (size_t)h * rstep + koff);
            CP_ASYNC16(st + TILE_B + sro[h],     gAl + (size_t)h * rstep + koff);
            CP_ASYNC16(st + 2 * TILE_B + sro[h], gBh + (size_t)h * rstep + koff);
            CP_ASYNC16(st + 3 * TILE_B + sro[h], gBl + (size_t)h * rstep + koff);
        }
        CP_COMMIT();
    };

    PDL_WAIT();
    load_chunk(0, 0);
    load_chunk(1, 1);
    int lbuf = 2, cbuf = 0;

    for (int c = 0; c < NC; c++) {
        if (c + 1 < NC) { CP_WAIT(1); } else { CP_WAIT(0); }
        __syncthreads();
        if (c + 2 < NC) {
            load_chunk(c + 2, lbuf);
            lbuf = (lbuf == 2) ? 0 : lbuf + 1;
        }

        const uint32_t st  = sbase + cbuf * STAGE_B;
        cbuf = (cbuf == 2) ? 0 : cbuf + 1;
        const uint32_t aBh = st,              aBl = st + TILE_B;
        const uint32_t bBh = st + 2 * TILE_B, bBl = st + 3 * TILE_B;

#pragma unroll
        for (int ks = 0; ks < 2; ks++) {
            const uint32_t aoff = (uint32_t)(aRowB * 64 +
                                  (((ks * 2 + aKc0) ^ aSw) << 4));
            const uint32_t boff = (uint32_t)(bRowB * 64 +
                                  (((ks * 2 + bKc0) ^ bSw) << 4));

            uint32_t bh[4][2], bl[4][2];
#pragma unroll
            for (int j2 = 0; j2 < 2; j2++) {
                uint32_t r0, r1, r2, r3;
                LDMATRIX_X4(r0, r1, r2, r3, bBh + boff + j2 * 1024);
                bh[j2 * 2 + 0][0] = r0; bh[j2 * 2 + 0][1] = r1;
                bh[j2 * 2 + 1][0] = r2; bh[j2 * 2 + 1][1] = r3;
                LDMATRIX_X4(r0, r1, r2, r3, bBl + boff + j2 * 1024);
                bl[j2 * 2 + 0][0] = r0; bl[j2 * 2 + 0][1] = r1;
                bl[j2 * 2 + 1][0] = r2; bl[j2 * 2 + 1][1] = r3;
            }
            uint32_t a[4][4];
#pragma unroll
            for (int i = 0; i < 4; i++)
                LDMATRIX_X4(a[i][0], a[i][1], a[i][2], a[i][3],
                            aBh + aoff + i * 1024);
#pragma unroll
            for (int i = 0; i < 4; i++)
#pragma unroll
                for (int j = 0; j < 4; j++)
                    MMA_BF16(acc[i][j][0], acc[i][j][1], acc[i][j][2], acc[i][j][3],
                             a[i][0], a[i][1], a[i][2], a[i][3], bh[j][0], bh[j][1]);
#pragma unroll
            for (int i = 0; i < 4; i++)
#pragma unroll
                for (int j = 0; j < 4; j++)
                    MMA_BF16(acc[i][j][0], acc[i][j][1], acc[i][j][2], acc[i][j][3],
                             a[i][0], a[i][1], a[i][2], a[i][3], bl[j][0], bl[j][1]);
#pragma unroll
            for (int i = 0; i < 4; i++)
                LDMATRIX_X4(a[i][0], a[i][1], a[i][2], a[i][3],
                            aBl + aoff + i * 1024);
#pragma unroll
            for (int i = 0; i < 4; i++)
#pragma unroll
                for (int j = 0; j < 4; j++)
                    MMA_BF16(acc[i][j][0], acc[i][j][1], acc[i][j][2], acc[i][j][3],
                             a[i][0], a[i][1], a[i][2], a[i][3], bh[j][0], bh[j][1]);
        }
    }

    const int tg = lane >> 2;
    const int tc = (lane & 3) * 2;
#pragma unroll
    for (int i = 0; i < 4; i++) {
        const int r0 = bm + wm * 64 + i * 16 + tg;
#pragma unroll
        for (int j = 0; j < 4; j++) {
            const int col = bn + wn * 32 + j * 8 + tc;
            float v0 = acc[i][j][0], v1 = acc[i][j][1];
            float v2 = acc[i][j][2], v3 = acc[i][j][3];
            if (BIAS) {
                const float b0 = bias[col], b1 = bias[col + 1];
                v0 += b0; v1 += b1; v2 += b0; v3 += b1;
            }
            if (LEAKY) {
                v0 = v0 > 0.f ? v0 : 0.01f * v0;
                v1 = v1 > 0.f ? v1 : 0.01f * v1;
                v2 = v2 > 0.f ? v2 : 0.01f * v2;
                v3 = v3 > 0.f ? v3 : 0.01f * v3;
            }
            if (SPLIT) {
                uint32_t h01, l01, h23, l23;
                split2(v0, v1, h01, l01);
                split2(v2, v3, h23, l23);
                *(uint32_t*)&Chi[(size_t)r0 * N + col]       = h01;
                *(uint32_t*)&Clo[(size_t)r0 * N + col]       = l01;
                *(uint32_t*)&Chi[(size_t)(r0 + 8) * N + col] = h23;
                *(uint32_t*)&Clo[(size_t)(r0 + 8) * N + col] = l23;
            } else {
                *(float2*)&C[(size_t)r0 * N + col]       = make_float2(v0, v1);
                *(float2*)&C[(size_t)(r0 + 8) * N + col] = make_float2(v2, v3);
            }
        }
    }
}

template <int BIAS, int LEAKY, int SPLIT>
__global__ void __launch_bounds__(256, 2)
gemm_hmma(const __nv_bfloat16* __restrict__ Ah, const __nv_bfloat16* __restrict__ Al,
          const __nv_bfloat16* __restrict__ Bh, const __nv_bfloat16* __restrict__ Bl,
          const float* __restrict__ bias, float* __restrict__ C,
          __nv_bfloat16* __restrict__ Chi, __nv_bfloat16* __restrict__ Clo,
          int N, int K)
{
    extern __shared__ __align__(16) char smem[];
    gemm_body<BIAS, LEAKY, SPLIT>(Ah, Al, Bh, Bl, bias, C, Chi, Clo,
                                  N, K, blockIdx.y * 128, blockIdx.x * 128, smem);
}

__global__ void __launch_bounds__(256, 2)
gemm_dual(const __nv_bfloat16* A0h, const __nv_bfloat16* A0l,
          const __nv_bfloat16* W0h, const __nv_bfloat16* W0l,
          __nv_bfloat16* C0h, __nv_bfloat16* C0l, int N0, int nb0,
          const __nv_bfloat16* A1h, const __nv_bfloat16* A1l,
          const __nv_bfloat16* W1h, const __nv_bfloat16* W1l,
          __nv_bfloat16* C1h, __nv_bfloat16* C1l, int N1, int K)
{
    extern __shared__ __align__(16) char smem[];
    if ((int)blockIdx.x < nb0)
        gemm_body<0, 0, 1>(A0h, A0l, W0h, W0l, nullptr, nullptr, C0h, C0l,
                           N0, K, blockIdx.y * 128, blockIdx.x * 128, smem);
    else
        gemm_body<0, 0, 1>(A1h, A1l, W1h, W1l, nullptr, nullptr, C1h, C1l,
                           N1, K, blockIdx.y * 128, (blockIdx.x - nb0) * 128, smem);
}

// ---------------------------------------------------------------------------
// HMMA flash attention, split-bf16, cp.async 2-stage K/V pipeline.
// ---------------------------------------------------------------------------
#define AROWB 144
#define KV_STAGE 36864                         // Kh,Kl,Vh,Vl each 64*144
#define ATT_SMEM (2 * 18432 + 2 * KV_STAGE)    // Q(h,l) + 2 KV stages = 110592

__global__ void __launch_bounds__(256, 2)
attn_hmma(const __nv_bfloat16* __restrict__ Qh, const __nv_bfloat16* __restrict__ Ql,
          int qs,
          const __nv_bfloat16* __restrict__ Kh, const __nv_bfloat16* __restrict__ Kl,
          const __nv_bfloat16* __restrict__ Vh, const __nv_bfloat16* __restrict__ Vl,
          int kvs,
          const int* __restrict__ vlp, int per_row,
          __nv_bfloat16* __restrict__ Oh, __nv_bfloat16* __restrict__ Ol)
{
    PDL_TRIGGER();
    extern __shared__ __align__(16) char sm[];
    char* cQh = sm;
    char* cQl = sm + 18432;
    const uint32_t uQh = smem_u32(cQh), uQl = smem_u32(cQl);
    const uint32_t uKV = smem_u32(sm + 36864);
    __shared__ int sred[8];

    const int tid = threadIdx.x;
    const int w = tid >> 5, lane = tid & 31;
    const int g = lane >> 2, c = lane & 3;
    const int b = blockIdx.x >> 3, h = blockIdx.x & 7;
    const int q0 = blockIdx.y * 128;

    // valid-len reduction reads harness inputs only -> safe before PDL_WAIT
    int kmax;
    if (per_row) {
        int v = (tid < 128) ? vlp[b * T_ + q0 + tid] : 0;
#pragma unroll
        for (int off = 16; off; off >>= 1)
            v = max(v, __shfl_xor_sync(0xffffffffu, v, off));
        if (lane == 0) sred[w] = v;
        __syncthreads();
        kmax = sred[0];
#pragma unroll
        for (int i = 1; i < 8; i++) kmax = max(kmax, sred[i]);
    } else {
        kmax = vlp[b];
    }
    const int nkt = (kmax + 63) >> 6;

    int vl0, vl1;
    if (per_row) {
        vl0 = vlp[b * T_ + q0 + w * 16 + g];
        vl1 = vlp[b * T_ + q0 + w * 16 + g + 8];
    } else {
        vl0 = vl1 = kmax;
    }

    PDL_WAIT();

    // load Q tiles (synchronous, once)
    const __nv_bfloat16* qhp = Qh + (size_t)(b * T_ + q0) * qs + h * 64;
    const __nv_bfloat16* qlp = Ql + (size_t)(b * T_ + q0) * qs + h * 64;
    for (int i = tid; i < 1024; i += 256) {
        const int r = i >> 3, ch = i & 7;
        const size_t go = (size_t)r * qs + ch * 8;
        const uint32_t so = r * AROWB + ch * 16;
        *(uint4*)(cQh + so) = *(const uint4*)(qhp + go);
        *(uint4*)(cQl + so) = *(const uint4*)(qlp + go);
    }

    auto load_kv = [&](int kt, int stg) {
        const size_t kb = (size_t)(b * T_ + kt * 64) * kvs + h * 64;
        const uint32_t sb = uKV + stg * KV_STAGE;
        for (int i = tid; i < 512; i += 256) {
            const int r = i >> 3, ch = i & 7;
            const size_t go = kb + (size_t)r * kvs + ch * 8;
            const uint32_t so = r * AROWB + ch * 16;
            CP_ASYNC16(sb + so,         Kh + go);
            CP_ASYNC16(sb + 9216 + so,  Kl + go);
            CP_ASYNC16(sb + 18432 + so, Vh + go);
            CP_ASYNC16(sb + 27648 + so, Vl + go);
        }
        CP_COMMIT();
    };
    load_kv(0, 0);

    float m0 = -1e30f, m1 = -1e30f, l0 = 0.f, l1 = 0.f;
    float o[8][4];
#pragma unroll
    for (int j = 0; j < 8; j++)
#pragma unroll
        for (int e = 0; e < 4; e++) o[j][e] = 0.f;

    const uint32_t qaddr = (w * 16 + (lane & 15)) * AROWB + (lane >> 4) * 16;
    const int bRow = (lane & 7) + ((lane >> 4) << 3);
    const int bK8  = ((lane >> 3) & 1) * 16;
    const int vRow = (lane & 7) + ((lane >> 3) & 1) * 8;
    const int vColB = (lane >> 4) * 16;

    for (int kt = 0; kt < nkt; kt++) {
        __syncthreads();                 // all readers of the other stage done
        if (kt + 1 < nkt) {
            load_kv(kt + 1, (kt + 1) & 1);
            CP_WAIT(1);
        } else {
            CP_WAIT(0);
        }
        __syncthreads();                 // stage kt&1 visible to all warps

        const uint32_t sK  = uKV + (kt & 1) * KV_STAGE;
        const uint32_t uKh = sK, uKl = sK + 9216;
        const uint32_t uVh = sK + 18432, uVl = sK + 27648;

        float s[8][4];
#pragma unroll
        for (int j = 0; j < 8; j++)
#pragma unroll
            for (int e = 0; e < 4; e++) s[j][e] = 0.f;

#pragma unroll
        for (int kk = 0; kk < 4; kk++) {
            uint32_t ah0, ah1, ah2, ah3, al0, al1, al2, al3;
            LDMATRIX_X4(ah0, ah1, ah2, ah3, uQh + qaddr + kk * 32);
            LDMATRIX_X4(al0, al1, al2, al3, uQl + qaddr + kk * 32);
#pragma unroll
            for (int j2 = 0; j2 < 4; j2++) {
                uint32_t r0, r1, r2, r3;
                LDMATRIX_X4(r0, r1, r2, r3,
                            uKh + (j2 * 16 + bRow) * AROWB + kk * 32 + bK8);
                MMA_BF16(s[2*j2][0], s[2*j2][1], s[2*j2][2], s[2*j2][3],
                         ah0, ah1, ah2, ah3, r0, r1);
                MMA_BF16(s[2*j2+1][0], s[2*j2+1][1], s[2*j2+1][2], s[2*j2+1][3],
                         ah0, ah1, ah2, ah3, r2, r3);
                MMA_BF16(s[2*j2][0], s[2*j2][1], s[2*j2][2], s[2*j2][3],
                         al0, al1, al2, al3, r0, r1);
                MMA_BF16(s[2*j2+1][0], s[2*j2+1][1], s[2*j2+1][2], s[2*j2+1][3],
                         al0, al1, al2, al3, r2, r3);
            }
#pragma unroll
            for (int j2 = 0; j2 < 4; j2++) {
                uint32_t r0, r1, r2, r3;
                LDMATRIX_X4(r0, r1, r2, r3,
                            uKl + (j2 * 16 + bRow) * AROWB + kk * 32 + bK8);
                MMA_BF16(s[2*j2][0], s[2*j2][1], s[2*j2][2], s[2*j2][3],
                         ah0, ah1, ah2, ah3, r0, r1);
                MMA_BF16(s[2*j2+1][0], s[2*j2+1][1], s[2*j2+1][2], s[2*j2+1][3],
                         ah0, ah1, ah2, ah3, r2, r3);
            }
        }

        const int kof = kt * 64 + c * 2;
        float mx0 = -1e30f, mx1 = -1e30f;
#pragma unroll
        for (int j = 0; j < 8; j++) {
            const int ki = kof + j * 8;
            s[j][0] = (ki     < vl0) ? s[j][0] * 0.125f : -1e10f;
            s[j][1] = (ki + 1 < vl0) ? s[j][1] * 0.125f : -1e10f;
            s[j][2] = (ki     < vl1) ? s[j][2] * 0.125f : -1e10f;
            s[j][3] = (ki + 1 < vl1) ? s[j][3] * 0.125f : -1e10f;
            mx0 = fmaxf(mx0, fmaxf(s[j][0], s[j][1]));
            mx1 = fmaxf(mx1, fmaxf(s[j][2], s[j][3]));
        }
        mx0 = fmaxf(mx0, __shfl_xor_sync(0xffffffffu, mx0, 1));
        mx0 = fmaxf(mx0, __shfl_xor_sync(0xffffffffu, mx0, 2));
        mx1 = fmaxf(mx1, __shfl_xor_sync(0xffffffffu, mx1, 1));
        mx1 = fmaxf(mx1, __shfl_xor_sync(0xffffffffu, mx1, 2));

        const float mn0 = fmaxf(m0, mx0), mn1 = fmaxf(m1, mx1);
        const float al_0 = __expf(m0 - mn0), al_1 = __expf(m1 - mn1);
        m0 = mn0; m1 = mn1;

        float rs0 = 0.f, rs1 = 0.f;
#pragma unroll
        for (int j = 0; j < 8; j++) {
            s[j][0] = __expf(s[j][0] - mn0);
            s[j][1] = __expf(s[j][1] - mn0);
            s[j][2] = __expf(s[j][2] - mn1);
            s[j][3] = __expf(s[j][3] - mn1);
            rs0 += s[j][0] + s[j][1];
            rs1 += s[j][2] + s[j][3];
        }
        rs0 += __shfl_xor_sync(0xffffffffu, rs0, 1);
        rs0 += __shfl_xor_sync(0xffffffffu, rs0, 2);
        rs1 += __shfl_xor_sync(0xffffffffu, rs1, 1);
        rs1 += __shfl_xor_sync(0xffffffffu, rs1, 2);
        l0 = l0 * al_0 + rs0;
        l1 = l1 * al_1 + rs1;

#pragma unroll
        for (int j = 0; j < 8; j++) {
            o[j][0] *= al_0; o[j][1] *= al_0;
            o[j][2] *= al_1; o[j][3] *= al_1;
        }

#pragma unroll
        for (int t = 0; t < 4; t++) {
            uint32_t ph[4], pl[4];
            split2(s[2*t][0],   s[2*t][1],   ph[0], pl[0]);
            split2(s[2*t][2],   s[2*t][3],   ph[1], pl[1]);
            split2(s[2*t+1][0], s[2*t+1][1], ph[2], pl[2]);
            split2(s[2*t+1][2], s[2*t+1][3], ph[3], pl[3]);
#pragma unroll
            for (int j2 = 0; j2 < 4; j2++) {
                uint32_t r0, r1, r2, r3;
                LDMATRIX_X4_T(r0, r1, r2, r3,
                              uVh + (t * 16 + vRow) * AROWB + j2 * 32 + vColB);
                MMA_BF16(o[2*j2][0], o[2*j2][1], o[2*j2][2], o[2*j2][3],
                         ph[0], ph[1], ph[2], ph[3], r0, r1);
                MMA_BF16(o[2*j2+1][0], o[2*j2+1][1], o[2*j2+1][2], o[2*j2+1][3],
                         ph[0], ph[1], ph[2], ph[3], r2, r3);
                MMA_BF16(o[2*j2][0], o[2*j2][1], o[2*j2][2], o[2*j2][3],
                         pl[0], pl[1], pl[2], pl[3], r0, r1);
                MMA_BF16(o[2*j2+1][0], o[2*j2+1][1], o[2*j2+1][2], o[2*j2+1][3],
                         pl[0], pl[1], pl[2], pl[3], r2, r3);
            }
#pragma unroll
            for (int j2 = 0; j2 < 4; j2++) {
                uint32_t r0, r1, r2, r3;
                LDMATRIX_X4_T(r0, r1, r2, r3,
                              uVl + (t * 16 + vRow) * AROWB + j2 * 32 + vColB);
                MMA_BF16(o[2*j2][0], o[2*j2][1], o[2*j2][2], o[2*j2][3],
                         ph[0], ph[1], ph[2], ph[3], r0, r1);
                MMA_BF16(o[2*j2+1][0], o[2*j2+1][1], o[2*j2+1][2], o[2*j2+1][3],
                         ph[0], ph[1], ph[2], ph[3], r2, r3);
            }
        }
    }

    const float il0 = 1.0f / l0, il1 = 1.0f / l1;
    const int r0g = b * T_ + q0 + w * 16 + g;
    const int r1g = r0g + 8;
#pragma unroll
    for (int j = 0; j < 8; j++) {
        const int col = h * 64 + j * 8 + c * 2;
        uint32_t hi, lo;
        split2(o[j][0] * il0, o[j][1] * il0, hi, lo);
        *(uint32_t*)&Oh[(size_t)r0g * D_ + col] = hi;
        *(uint32_t*)&Ol[(size_t)r0g * D_ + col] = lo;
        split2(o[j][2] * il1, o[j][3] * il1, hi, lo);
        *(uint32_t*)&Oh[(size_t)r1g * D_ + col] = hi;
        *(uint32_t*)&Ol[(size_t)r1g * D_ + col] = lo;
    }
}

// ---------------------------------------------------------------------------
// out = LayerNorm(A + Bt) * g + be ; SPLIT=1 also emits bf16 hi/lo
// ---------------------------------------------------------------------------
template <int SPLIT>
__global__ void __launch_bounds__(128)
addnorm_kernel(const float* __restrict__ A, const float* __restrict__ Bt,
               const float* __restrict__ g, const float* __restrict__ be,
               float* __restrict__ out,
               __nv_bfloat16* __restrict__ ohi, __nv_bfloat16* __restrict__ olo)
{
    PDL_TRIGGER();
    PDL_WAIT();
    const int row = blockIdx.x;
    const int tid = threadIdx.x;
    const size_t base = (size_t)row * D_;

    float4 a = *(const float4*)&A[base + tid * 4];
    float4 b = *(const float4*)&Bt[base + tid * 4];
    float4 x = make_float4(a.x + b.x, a.y + b.y, a.z + b.z, a.w + b.w);

    float s  = x.x + x.y + x.z + x.w;
    float sq = x.x * x.x + x.y * x.y + x.z * x.z + x.w * x.w;
#pragma unroll
    for (int off = 16; off; off >>= 1) {
        s  += __shfl_xor_sync(0xffffffffu, s,  off);
        sq += __shfl_xor_sync(0xffffffffu, sq, off);
    }
    __shared__ float ss[4], ssq[4];
    if ((tid & 31) == 0) { ss[tid >> 5] = s; ssq[tid >> 5] = sq; }
    __syncthreads();
    s  = ss[0] + ss[1] + ss[2] + ss[3];
    sq = ssq[0] + ssq[1] + ssq[2] + ssq[3];

    float mu  = s * (1.0f / D_);
    float var = sq * (1.0f / D_) - mu * mu;
    float inv = rsqrtf(var + 1e-5f);

    float4 gg = *(const float4*)&g[tid * 4];
    float4 bb = *(const float4*)&be[tid * 4];
    float4 oo = make_float4((x.x - mu) * inv * gg.x + bb.x,
                            (x.y - mu) * inv * gg.y + bb.y,
                            (x.z - mu) * inv * gg.z + bb.z,
                            (x.w - mu) * inv * gg.w + bb.w);
    *(float4*)&out[base + tid * 4] = oo;
    if (SPLIT) {
        uint32_t h0, l0, h1, l1;
        split2(oo.x, oo.y, h0, l0);
        split2(oo.z, oo.w, h1, l1);
        uint32_t* hp = (uint32_t*)&ohi[base + tid * 4];
        uint32_t* lp = (uint32_t*)&olo[base + tid * 4];
        hp[0] = h0; hp[1] = h1;
        lp[0] = l0; lp[1] = l1;
    }
}

// ---------------------------------------------------------------------------
// PDL launch helper
// ---------------------------------------------------------------------------
template <typename... ExpT, typename... ActT>
static void launch_pdl(void (*kern)(ExpT...), dim3 gr, dim3 bl, size_t shm,
                       ActT... args)
{
    cudaLaunchConfig_t cfg = {};
    cfg.gridDim = gr;
    cfg.blockDim = bl;
    cfg.dynamicSmemBytes = shm;
    cfg.stream = 0;
    cudaLaunchAttribute at[1];
    at[0].id = cudaLaunchAttributeProgrammaticStreamSerialization;
    at[0].val.programmaticStreamSerializationAllowed = 1;
    cfg.attrs = at;
    cfg.numAttrs = 1;
    cudaLaunchKernelEx(&cfg, kern, args...);
}

// ---------------------------------------------------------------------------
// Launch
// ---------------------------------------------------------------------------
extern "C" void kernel_launch(void* const* d_in, const int* in_sizes, int n_in,
                              void* d_out, int out_size)
{
    const float* X    = (const float*)d_in[0];
    const float* ENC  = (const float*)d_in[1];
    const int*   DVL  = (const int*)d_in[2];
    const int*   EVL  = (const int*)d_in[3];
    const float* Wmat[8] = {
        (const float*)d_in[4],  (const float*)d_in[5],
        (const float*)d_in[6],  (const float*)d_in[7],
        (const float*)d_in[8],  (const float*)d_in[9],
        (const float*)d_in[10], (const float*)d_in[11]};
    const float* W1   = (const float*)d_in[12];
    const float* b1   = (const float*)d_in[13];
    const float* W2   = (const float*)d_in[14];
    const float* b2   = (const float*)d_in[15];
    const float* G1   = (const float*)d_in[16];
    const float* BE1  = (const float*)d_in[17];
    const float* G2   = (const float*)d_in[18];
    const float* BE2  = (const float*)d_in[19];
    const float* G3   = (const float*)d_in[20];
    const float* BE3  = (const float*)d_in[21];
    float* out = (float*)d_out;

    float *tmp, *Y, *Z;
    __nv_bfloat16 *h1, *l1, *h2, *l2, *qkvh, *qkvl, *kvh, *kvl;
    __nv_bfloat16 *q2h, *q2l, *ath, *atl, *Fh, *Fl, *Wh, *Wl;
    cudaGetSymbolAddress((void**)&tmp,  g_tmp);
    cudaGetSymbolAddress((void**)&Y,    g_Y);
    cudaGetSymbolAddress((void**)&Z,    g_Z);
    cudaGetSymbolAddress((void**)&h1,   g_h1);
    cudaGetSymbolAddress((void**)&l1,   g_l1);
    cudaGetSymbolAddress((void**)&h2,   g_h2);
    cudaGetSymbolAddress((void**)&l2,   g_l2);
    cudaGetSymbolAddress((void**)&qkvh, g_qkvh);
    cudaGetSymbolAddress((void**)&qkvl, g_qkvl);
    cudaGetSymbolAddress((void**)&kvh,  g_kvh);
    cudaGetSymbolAddress((void**)&kvl,  g_kvl);
    cudaGetSymbolAddress((void**)&q2h,  g_q2h);
    cudaGetSymbolAddress((void**)&q2l,  g_q2l);
    cudaGetSymbolAddress((void**)&ath,  g_ath);
    cudaGetSymbolAddress((void**)&atl,  g_atl);
    cudaGetSymbolAddress((void**)&Fh,   g_Fh);
    cudaGetSymbolAddress((void**)&Fl,   g_Fl);
    cudaGetSymbolAddress((void**)&Wh,   g_Wh);
    cudaGetSymbolAddress((void**)&Wl,   g_Wl);

    cudaFuncSetAttribute(attn_hmma,
                         cudaFuncAttributeMaxDynamicSharedMemorySize, ATT_SMEM);
    cudaFuncSetAttribute(gemm_hmma<0, 0, 1>,
                         cudaFuncAttributeMaxDynamicSharedMemorySize, GEMM_SMEM);
    cudaFuncSetAttribute(gemm_hmma<0, 0, 0>,
                         cudaFuncAttributeMaxDynamicSharedMemorySize, GEMM_SMEM);
    cudaFuncSetAttribute(gemm_hmma<1, 1, 1>,
                         cudaFuncAttributeMaxDynamicSharedMemorySize, GEMM_SMEM);
    cudaFuncSetAttribute(gemm_hmma<1, 0, 0>,
                         cudaFuncAttributeMaxDynamicSharedMemorySize, GEMM_SMEM);
    cudaFuncSetAttribute(gemm_dual,
                         cudaFuncAttributeMaxDynamicSharedMemorySize, GEMM_SMEM);

    size_t WO[10];
    for (int i = 0; i < 8; i++) WO[i] = (size_t)i * D_ * D_;
    WO[8] = 8ull * D_ * D_;
    WO[9] = WO[8] + (size_t)F_ * D_;

    const int nDD = D_ * D_ / 4;       // 65536
    const int nMD = M_ * D_ / 4;       // 2097152
    const int nFD = F_ * D_ / 4;       // 262144

    SplitSegs segs;
    int total4 = 0;
    for (int i = 0; i < 8; i++) {
        segs.src[i] = Wmat[i];
        segs.hi[i] = Wh + WO[i]; segs.lo[i] = Wl + WO[i];
        segs.n4[i] = nDD; total4 += nDD;
    }
    segs.src[8] = W1; segs.hi[8] = Wh + WO[8]; segs.lo[8] = Wl + WO[8];
    segs.n4[8] = nFD; total4 += nFD;
    segs.src[9] = W2; segs.hi[9] = Wh + WO[9]; segs.lo[9] = Wl + WO[9];
    segs.n4[9] = nFD; total4 += nFD;
    segs.src[10] = X;   segs.hi[10] = h1; segs.lo[10] = l1;
    segs.n4[10] = nMD; total4 += nMD;
    segs.src[11] = ENC; segs.hi[11] = h2; segs.lo[11] = l2;
    segs.n4[11] = nMD; total4 += nMD;
    launch_pdl(msplit_kernel, dim3((total4 + 255) / 256), dim3(256), 0, segs);

    dim3 gQKV(1536 / 128, M_ / 128);   // (12, 128)
    dim3 gDUO(12,         M_ / 128);   // q2(4) + kv(8)
    dim3 gP  (D_ / 128,   M_ / 128);   // (4, 128)
    dim3 gF1 (F_ / 128,   M_ / 128);   // (16, 128)
    dim3 gA  (B_ * H_,    T_ / 128);   // (256, 4)
    dim3 gAN (M_);

    // ---- self-attention ----
    launch_pdl(gemm_hmma<0,0,1>, gQKV, dim3(256), GEMM_SMEM,
               (const __nv_bfloat16*)h1, (const __nv_bfloat16*)l1,
               (const __nv_bfloat16*)(Wh + WO[0]), (const __nv_bfloat16*)(Wl + WO[0]),
               (const float*)nullptr, (float*)nullptr, qkvh, qkvl, 1536, D_);
    launch_pdl(attn_hmma, gA, dim3(256), (size_t)ATT_SMEM,
               (const __nv_bfloat16*)qkvh, (const __nv_bfloat16*)qkvl, 1536,
               (const __nv_bfloat16*)(qkvh + 512), (const __nv_bfloat16*)(qkvl + 512),
               (const __nv_bfloat16*)(qkvh + 1024), (const __nv_bfloat16*)(qkvl + 1024), 1536,
               DVL, 1, ath, atl);
    launch_pdl(gemm_hmma<0,0,0>, gP, dim3(256), GEMM_SMEM,
               (const __nv_bfloat16*)ath, (const __nv_bfloat16*)atl,
               (const __nv_bfloat16*)(Wh + WO[3]), (const __nv_bfloat16*)(Wl + WO[3]),
               (const float*)nullptr, tmp, (__nv_bfloat16*)nullptr, (__nv_bfloat16*)nullptr,
               D_, D_);
    launch_pdl(addnorm_kernel<1>, gAN, dim3(128), 0,
               X, (const float*)tmp, G1, BE1, Y, h1, l1);

    // ---- cross-attention (Q2 + KV in one launch) ----
    launch_pdl(gemm_dual, gDUO, dim3(256), GEMM_SMEM,
               (const __nv_bfloat16*)h1, (const __nv_bfloat16*)l1,
               (const __nv_bfloat16*)(Wh + WO[4]), (const __nv_bfloat16*)(Wl + WO[4]),
               q2h, q2l, 512, 4,
               (const __nv_bfloat16*)h2, (const __nv_bfloat16*)l2,
               (const __nv_bfloat16*)(Wh + WO[5]), (const __nv_bfloat16*)(Wl + WO[5]),
               kvh, kvl, 1024, D_);
    launch_pdl(attn_hmma, gA, dim3(256), (size_t)ATT_SMEM,
               (const __nv_bfloat16*)q2h, (const __nv_bfloat16*)q2l, D_,
               (const __nv_bfloat16*)kvh, (const __nv_bfloat16*)kvl,
               (const __nv_bfloat16*)(kvh + 512), (const __nv_bfloat16*)(kvl + 512), 1024,
               EVL, 0, ath, atl);
    launch_pdl(gemm_hmma<0,0,0>, gP, dim3(256), GEMM_SMEM,
               (const __nv_bfloat16*)ath, (const __nv_bfloat16*)atl,
               (const __nv_bfloat16*)(Wh + WO[7]), (const __nv_bfloat16*)(Wl + WO[7]),
               (const float*)nullptr, tmp, (__nv_bfloat16*)nullptr, (__nv_bfloat16*)nullptr,
               D_, D_);
    launch_pdl(addnorm_kernel<1>, gAN, dim3(128), 0,
               (const float*)Y, (const float*)tmp, G2, BE2, Z, h2, l2);

    // ---- FFN ----
    launch_pdl(gemm_hmma<1,1,1>, gF1, dim3(256), GEMM_SMEM,
               (const __nv_bfloat16*)h2, (const __nv_bfloat16*)l2,
               (const __nv_bfloat16*)(Wh + WO[8]), (const __nv_bfloat16*)(Wl + WO[8]),
               b1, (float*)nullptr, Fh, Fl, F_, D_);
    launch_pdl(gemm_hmma<1,0,0>, gP, dim3(256), GEMM_SMEM,
               (const __nv_bfloat16*)Fh, (const __nv_bfloat16*)Fl,
               (const __nv_bfloat16*)(Wh + WO[9]), (const __nv_bfloat16*)(Wl + WO[9]),
               b2, tmp, (__nv_bfloat16*)nullptr, (__nv_bfloat16*)nullptr, D_, F_);
    launch_pdl(addnorm_kernel<0>, gAN, dim3(128), 0,
               (const float*)Z, (const float*)tmp, G3, BE3, out,
               (__nv_bfloat16*)nullptr, (__nv_bfloat16*)nullptr);
}